// round 5
// baseline (speedup 1.0000x reference)
#include <cuda_runtime.h>
#include <math.h>
#include <stdint.h>

// Problem constants
constexpr int NN  = 16384;   // nodes
constexpr int DD  = 128;     // dim
constexpr int EE  = 262144;  // edges
constexpr int SEQ = 512;     // nodes per graph
constexpr int NGR = 32;      // graphs
constexpr int NH  = 8;       // heads (dh = 16)

// ---------------- scratch ----------------
__device__ float g_z   [NN * DD];
__device__ float g_hl  [NN * DD];
__device__ float g_qkv [NN * 3 * DD];
__device__ float g_ao  [NN * DD];
__device__ float g_ha  [NN * DD];
__device__ float g_h   [NN * DD];
__device__ float g_h2  [NN * DD];
__device__ float g_stats[768];   // [0:256) hl, [256:512) ha, [512:768) h2
__device__ int   g_deg [NN];
__device__ int   g_off [NN + 1];
__device__ int   g_pos [NN];
__device__ int   g_eid [EE];

// =====================================================================
__global__ void zero_misc(int* deg, float* stats)
{
    int i = blockIdx.x * 256 + threadIdx.x;
    deg[i] = 0;
    if (i < 768) stats[i] = 0.f;
}

// =====================================================================
// CSR build by dst:  count -> scan -> scatter
// =====================================================================
__global__ void count_kernel(const int* __restrict__ dst, int* __restrict__ deg)
{
    int e = blockIdx.x * 256 + threadIdx.x;
    atomicAdd(&deg[dst[e]], 1);
}

__global__ void __launch_bounds__(1024)
scan_kernel(const int* __restrict__ deg, int* __restrict__ off, int* __restrict__ pos)
{
    __shared__ int buf[2][1024];
    int t = threadIdx.x;
    int base = t * 16;
    int loc[16];
    int sum = 0;
#pragma unroll
    for (int i = 0; i < 16; ++i) { loc[i] = sum; sum += deg[base + i]; }
    buf[0][t] = sum;
    __syncthreads();
    int sel = 0;
    for (int d = 1; d < 1024; d <<= 1) {
        int v = buf[sel][t] + (t >= d ? buf[sel][t - d] : 0);
        buf[sel ^ 1][t] = v;
        sel ^= 1;
        __syncthreads();
    }
    int excl = buf[sel][t] - sum;
#pragma unroll
    for (int i = 0; i < 16; ++i) {
        int o = excl + loc[i];
        off[base + i] = o;
        pos[base + i] = o;
    }
    if (t == 1023) off[NN] = excl + sum;
}

__global__ void scatter_kernel(const int* __restrict__ dst, int* __restrict__ pos,
                               int* __restrict__ eid)
{
    int e = blockIdx.x * 256 + threadIdx.x;
    int p = atomicAdd(&pos[dst[e]], 1);
    eid[p] = e;
}

// =====================================================================
// Gather aggregation: z = x + sum_{e -> node} relu(x[src[e]] + ea[e])
// =====================================================================
__global__ void __launch_bounds__(256)
aggr_kernel(const float* __restrict__ x, const int* __restrict__ src,
            const float* __restrict__ ea, const int* __restrict__ off,
            const int* __restrict__ eid, float* __restrict__ z)
{
    int node = blockIdx.x * 8 + (threadIdx.x >> 5);
    int lane = threadIdx.x & 31;
    int beg = off[node], end = off[node + 1];
    const float4* x4  = (const float4*)x;
    const float4* ea4 = (const float4*)ea;
    float4 acc = make_float4(0.f, 0.f, 0.f, 0.f);
#pragma unroll 2
    for (int i = beg; i < end; ++i) {
        int e = __ldg(eid + i);
        int s = __ldg(src + e);
        float4 a = x4[(size_t)s * 32 + lane];
        float4 b = ea4[(size_t)e * 32 + lane];
        acc.x += fmaxf(a.x + b.x, 0.f);
        acc.y += fmaxf(a.y + b.y, 0.f);
        acc.z += fmaxf(a.z + b.z, 0.f);
        acc.w += fmaxf(a.w + b.w, 0.f);
    }
    float4 xv = x4[(size_t)node * 32 + lane];
    ((float4*)z)[(size_t)node * 32 + lane] =
        make_float4(xv.x + acc.x, xv.y + acc.y, xv.z + acc.z, xv.w + acc.w);
}

// =====================================================================
// TF32 mma helpers
// =====================================================================
__device__ __forceinline__ uint32_t to_tf32(float f)
{
    uint32_t u;
    asm("cvt.rna.tf32.f32 %0, %1;" : "=r"(u) : "f"(f));
    return u;
}

__device__ __forceinline__ void mma_tf32(float c[4], const uint32_t a[4], const uint32_t b[2])
{
    asm volatile(
        "mma.sync.aligned.m16n8k8.row.col.f32.tf32.tf32.f32 "
        "{%0,%1,%2,%3}, {%4,%5,%6,%7}, {%8,%9}, {%0,%1,%2,%3};\n"
        : "+f"(c[0]), "+f"(c[1]), "+f"(c[2]), "+f"(c[3])
        : "r"(a[0]), "r"(a[1]), "r"(a[2]), "r"(a[3]), "r"(b[0]), "r"(b[1]));
}

constexpr int AST = 132;   // A/T smem stride (u32)
constexpr int BST = 20;    // B-chunk smem stride

// one 16-k-slab of mma: A-src (stride AST), B-chunk (stride BST)
__device__ __forceinline__ void mma_slab16(const uint32_t* S, const uint32_t* Bb,
                                           float acc[4][4][4],
                                           int wm, int wn, int g, int tig, int kt)
{
#pragma unroll
    for (int k8s = 0; k8s < 2; ++k8s) {
        const int kk = kt * 16 + k8s * 8;
        uint32_t af[4][4];
#pragma unroll
        for (int mf = 0; mf < 4; ++mf) {
            const uint32_t* pa = S + (wm * 64 + mf * 16 + g) * AST + kk + tig;
            af[mf][0] = pa[0];
            af[mf][1] = pa[8 * AST];
            af[mf][2] = pa[4];
            af[mf][3] = pa[8 * AST + 4];
        }
        uint32_t bf[4][2];
#pragma unroll
        for (int nf = 0; nf < 4; ++nf) {
            const uint32_t* pb = Bb + (wn * 32 + nf * 8 + g) * BST + k8s * 8 + tig;
            bf[nf][0] = pb[0];
            bf[nf][1] = pb[4];
        }
#pragma unroll
        for (int mf = 0; mf < 4; ++mf)
#pragma unroll
            for (int nf = 0; nf < 4; ++nf)
                mma_tf32(acc[mf][nf], af[mf], bf[nf]);
    }
}

// epilogue shared by gemm_ar / mlp_fused
template<bool RELU, bool RESID, bool STATS>
__device__ __forceinline__ void gemm_epilogue(
    float acc[4][4][4], const float* bias, const float* resid,
    float* C, int ldc, int m0, int n0,
    int wm, int wn, int g, int tig, int tid,
    float* stats, float* sst /* 256-float smem scratch */)
{
    float cs[8], cq[8];
    if (STATS) {
#pragma unroll
        for (int j = 0; j < 8; ++j) { cs[j] = 0.f; cq[j] = 0.f; }
    }
#pragma unroll
    for (int mf = 0; mf < 4; ++mf) {
#pragma unroll
        for (int nf = 0; nf < 4; ++nf) {
            int row = m0 + wm * 64 + mf * 16 + g;
            int col = n0 + wn * 32 + nf * 8 + 2 * tig;
            float b0 = bias[col], b1 = bias[col + 1];
            float o00 = acc[mf][nf][0] + b0, o01 = acc[mf][nf][1] + b1;
            float o10 = acc[mf][nf][2] + b0, o11 = acc[mf][nf][3] + b1;
            if (RELU) {
                o00 = fmaxf(o00, 0.f); o01 = fmaxf(o01, 0.f);
                o10 = fmaxf(o10, 0.f); o11 = fmaxf(o11, 0.f);
            }
            if (RESID) {
                float2 r0 = *(const float2*)(resid + (size_t)row * ldc + col);
                float2 r1 = *(const float2*)(resid + (size_t)(row + 8) * ldc + col);
                o00 += r0.x; o01 += r0.y;
                o10 += r1.x; o11 += r1.y;
            }
            if (STATS) {
                cs[nf*2]   += o00 + o10;
                cs[nf*2+1] += o01 + o11;
                cq[nf*2]   += o00*o00 + o10*o10;
                cq[nf*2+1] += o01*o01 + o11*o11;
            }
            *(float2*)(C + (size_t)row * ldc + col)       = make_float2(o00, o01);
            *(float2*)(C + (size_t)(row + 8) * ldc + col) = make_float2(o10, o11);
        }
    }
    if (STATS) {
        __syncthreads();
        sst[tid] = 0.f;
        __syncthreads();
#pragma unroll
        for (int j = 0; j < 8; ++j) {
            int col = wn * 32 + (j >> 1) * 8 + 2 * tig + (j & 1);
            atomicAdd(&sst[col],       cs[j]);
            atomicAdd(&sst[128 + col], cq[j]);
        }
        __syncthreads();
        atomicAdd(&stats[tid], sst[tid]);
    }
}

// =====================================================================
// A-resident GEMM (K=128): C = A[128rows,128] @ B^T + bias (+resid)(+stats)
// B is [ncols, 128] row-major (torch W). Prefetch-pipelined B chunks.
// =====================================================================
constexpr int GEMM_AR_SMEM = (128 * AST + 128 * BST) * 4;

template<bool RESID, bool STATS>
__global__ void __launch_bounds__(256, 2)
gemm_ar(const float* __restrict__ A,
        const float* __restrict__ B,
        const float* __restrict__ bias,
        const float* __restrict__ resid,
        float* __restrict__ C, int ldc,
        float* __restrict__ stats)
{
    extern __shared__ uint32_t sm[];
    uint32_t* Abuf = sm;               // [128][AST]
    uint32_t* Bbuf = sm + 128 * AST;   // [128][BST]

    const int tid = threadIdx.x;
    const int lane = tid & 31, warp = tid >> 5;
    const int wm = warp >> 2, wn = warp & 3;
    const int g = lane >> 2, tig = lane & 3;
    const int m0 = blockIdx.x * 128;
    const int n0 = blockIdx.y * 128;

    // stage A strip (coalesced: warp loads one 512B row)
#pragma unroll
    for (int it = 0; it < 16; ++it) {
        int idx = tid + it * 256;
        int r = idx >> 5, c4 = (idx & 31) * 4;
        float4 v = *(const float4*)(A + (size_t)(m0 + r) * 128 + c4);
        uint32_t* d = Abuf + r * AST + c4;
        d[0] = to_tf32(v.x); d[1] = to_tf32(v.y);
        d[2] = to_tf32(v.z); d[3] = to_tf32(v.w);
    }

    float acc[4][4][4];
#pragma unroll
    for (int i = 0; i < 4; ++i)
#pragma unroll
        for (int j = 0; j < 4; ++j)
#pragma unroll
            for (int r = 0; r < 4; ++r) acc[i][j][r] = 0.f;

    // prefetch B chunk 0 (trans layout: row n, 16 k) : 2 float4 per thread
    float4 pre0, pre1;
    {
        int i0 = tid, i1 = tid + 256;
        pre0 = *(const float4*)(B + (size_t)(n0 + (i0 >> 2)) * 128 + (i0 & 3) * 4);
        pre1 = *(const float4*)(B + (size_t)(n0 + (i1 >> 2)) * 128 + (i1 & 3) * 4);
    }

    for (int kt = 0; kt < 8; ++kt) {
        __syncthreads();
        {
            int i0 = tid, i1 = tid + 256;
            uint32_t* d0 = Bbuf + (i0 >> 2) * BST + (i0 & 3) * 4;
            d0[0] = to_tf32(pre0.x); d0[1] = to_tf32(pre0.y);
            d0[2] = to_tf32(pre0.z); d0[3] = to_tf32(pre0.w);
            uint32_t* d1 = Bbuf + (i1 >> 2) * BST + (i1 & 3) * 4;
            d1[0] = to_tf32(pre1.x); d1[1] = to_tf32(pre1.y);
            d1[2] = to_tf32(pre1.z); d1[3] = to_tf32(pre1.w);
        }
        if (kt < 7) {
            int i0 = tid, i1 = tid + 256;
            pre0 = *(const float4*)(B + (size_t)(n0 + (i0 >> 2)) * 128 + (kt + 1) * 16 + (i0 & 3) * 4);
            pre1 = *(const float4*)(B + (size_t)(n0 + (i1 >> 2)) * 128 + (kt + 1) * 16 + (i1 & 3) * 4);
        }
        __syncthreads();
        mma_slab16(Abuf, Bbuf, acc, wm, wn, g, tig, kt);
    }

    gemm_epilogue<false, RESID, STATS>(acc, bias, resid, C, ldc, m0, n0,
                                       wm, wn, g, tig, tid, stats, (float*)Bbuf);
}

// =====================================================================
// Fused MLP: C = relu(A @ W1 + b1) @ W2 + b2 (+resid)(+stats)
// A: [128rows, 128]; W1: [128, NC*128] row-major; W2: [NC*128, 128] row-major.
// Hidden tile lives in smem (tf32), never touches gmem.
// =====================================================================
constexpr int MLP_SMEM = (2 * 128 * AST + 128 * BST) * 4;

template<int NC, bool STATS>
__global__ void __launch_bounds__(256, 1)
mlp_fused(const float* __restrict__ A,
          const float* __restrict__ W1, const float* __restrict__ b1,
          const float* __restrict__ W2, const float* __restrict__ b2,
          const float* __restrict__ resid,
          float* __restrict__ C,
          float* __restrict__ stats)
{
    extern __shared__ uint32_t sm[];
    uint32_t* Abuf = sm;                   // [128][AST]
    uint32_t* Tbuf = sm + 128 * AST;       // [128][AST]
    uint32_t* Bbuf = sm + 2 * 128 * AST;   // [128][BST]

    const int tid = threadIdx.x;
    const int lane = tid & 31, warp = tid >> 5;
    const int wm = warp >> 2, wn = warp & 3;
    const int g = lane >> 2, tig = lane & 3;
    const int m0 = blockIdx.x * 128;
    const int ldw1 = NC * 128;

    // stage A strip
#pragma unroll
    for (int it = 0; it < 16; ++it) {
        int idx = tid + it * 256;
        int r = idx >> 5, c4 = (idx & 31) * 4;
        float4 v = *(const float4*)(A + (size_t)(m0 + r) * 128 + c4);
        uint32_t* d = Abuf + r * AST + c4;
        d[0] = to_tf32(v.x); d[1] = to_tf32(v.y);
        d[2] = to_tf32(v.z); d[3] = to_tf32(v.w);
    }

    float co[4][4][4];
#pragma unroll
    for (int i = 0; i < 4; ++i)
#pragma unroll
        for (int j = 0; j < 4; ++j)
#pragma unroll
            for (int r = 0; r < 4; ++r) co[i][j][r] = 0.f;

    const int kk = tid >> 7;        // 0..1 (k within pair)
    const int nn2 = tid & 127;      // n col

#pragma unroll
    for (int nc = 0; nc < NC; ++nc) {
        // ================= phase 1: c1 = A @ W1[:, nc*128..] =================
        float c1[4][4][4];
#pragma unroll
        for (int i = 0; i < 4; ++i)
#pragma unroll
            for (int j = 0; j < 4; ++j)
#pragma unroll
                for (int r = 0; r < 4; ++r) c1[i][j][r] = 0.f;

        float pre[8];
#pragma unroll
        for (int j = 0; j < 8; ++j)  // chunk 0: k = j*2 + kk
            pre[j] = W1[(size_t)(j * 2 + kk) * ldw1 + nc * 128 + nn2];

        for (int kt = 0; kt < 8; ++kt) {
            __syncthreads();
#pragma unroll
            for (int j = 0; j < 8; ++j)
                Bbuf[nn2 * BST + j * 2 + kk] = to_tf32(pre[j]);
            if (kt < 7) {
#pragma unroll
                for (int j = 0; j < 8; ++j)
                    pre[j] = W1[(size_t)((kt + 1) * 16 + j * 2 + kk) * ldw1 + nc * 128 + nn2];
            }
            __syncthreads();
            mma_slab16(Abuf, Bbuf, c1, wm, wn, g, tig, kt);
        }

        // write hidden tile: relu(c1 + b1chunk) -> Tbuf (tf32)
#pragma unroll
        for (int mf = 0; mf < 4; ++mf) {
#pragma unroll
            for (int nf = 0; nf < 4; ++nf) {
                int row = wm * 64 + mf * 16 + g;
                int col = wn * 32 + nf * 8 + 2 * tig;
                float bb0 = b1[nc * 128 + col], bb1 = b1[nc * 128 + col + 1];
                Tbuf[row * AST + col]           = to_tf32(fmaxf(c1[mf][nf][0] + bb0, 0.f));
                Tbuf[row * AST + col + 1]       = to_tf32(fmaxf(c1[mf][nf][1] + bb1, 0.f));
                Tbuf[(row + 8) * AST + col]     = to_tf32(fmaxf(c1[mf][nf][2] + bb0, 0.f));
                Tbuf[(row + 8) * AST + col + 1] = to_tf32(fmaxf(c1[mf][nf][3] + bb1, 0.f));
            }
        }

        // ================= phase 2: co += T @ W2[nc*128.., :] =================
#pragma unroll
        for (int j = 0; j < 8; ++j)
            pre[j] = W2[(size_t)(nc * 128 + j * 2 + kk) * 128 + nn2];

        for (int kt = 0; kt < 8; ++kt) {
            __syncthreads();
#pragma unroll
            for (int j = 0; j < 8; ++j)
                Bbuf[nn2 * BST + j * 2 + kk] = to_tf32(pre[j]);
            if (kt < 7) {
#pragma unroll
                for (int j = 0; j < 8; ++j)
                    pre[j] = W2[(size_t)(nc * 128 + (kt + 1) * 16 + j * 2 + kk) * 128 + nn2];
            }
            __syncthreads();
            mma_slab16(Tbuf, Bbuf, co, wm, wn, g, tig, kt);
        }
    }

    gemm_epilogue<false, true, STATS>(co, b2, resid, C, 128, m0, 0,
                                      wm, wn, g, tig, tid, stats, (float*)Bbuf);
}

// =====================================================================
// Flash-style TF32 tensor-core attention (unchanged from R3).
// =====================================================================
constexpr int KS_STRIDE = 20;
constexpr int VS_STRIDE = 24;
constexpr int P_STRIDE  = 36;
constexpr int ATTN_SMEM = (512 * KS_STRIDE + 512 * VS_STRIDE + 8 * 64 * P_STRIDE) * 4;

__global__ void __launch_bounds__(256, 1)
attn_mma(const float* __restrict__ qkv, float* __restrict__ ao)
{
    extern __shared__ uint32_t sm[];
    uint32_t* Ks = sm;
    uint32_t* Vs = sm + 512 * KS_STRIDE;
    uint32_t* Pa = Vs + 512 * VS_STRIDE;

    const int tid  = threadIdx.x;
    const int lane = tid & 31;
    const int warp = tid >> 5;
    const int g    = lane >> 2;
    const int tig  = lane & 3;
    const int gi = blockIdx.x >> 3, h = blockIdx.x & 7;
    const float* base = qkv + (size_t)gi * SEQ * 384;

    uint32_t* Pw = Pa + warp * 64 * P_STRIDE;
    const int m0 = warp * 64;

    for (int idx = tid; idx < 2048; idx += 256) {
        int r = idx >> 2, c4 = (idx & 3) * 4;
        float4 kv = *(const float4*)(base + (size_t)r * 384 + 128 + h * 16 + c4);
        float4 vv = *(const float4*)(base + (size_t)r * 384 + 256 + h * 16 + c4);
        uint32_t* kd = Ks + r * KS_STRIDE + c4;
        kd[0] = to_tf32(kv.x); kd[1] = to_tf32(kv.y);
        kd[2] = to_tf32(kv.z); kd[3] = to_tf32(kv.w);
        uint32_t* vd = Vs + r * VS_STRIDE + c4;
        vd[0] = to_tf32(vv.x); vd[1] = to_tf32(vv.y);
        vd[2] = to_tf32(vv.z); vd[3] = to_tf32(vv.w);
    }
#pragma unroll
    for (int i = 0; i < 8; ++i) {
        int idx = lane + i * 32;
        int r = idx >> 2, c4 = (idx & 3) * 4;
        float4 qv = *(const float4*)(base + (size_t)(m0 + r) * 384 + h * 16 + c4);
        *(float4*)((float*)Pw + r * P_STRIDE + c4) = qv;
    }
    __syncthreads();

    uint32_t qa[4][2][4];
#pragma unroll
    for (int mt = 0; mt < 4; ++mt)
#pragma unroll
        for (int ks = 0; ks < 2; ++ks) {
            const float* p = (const float*)Pw + (mt * 16 + g) * P_STRIDE + ks * 8 + tig;
            qa[mt][ks][0] = to_tf32(p[0] * 0.25f);
            qa[mt][ks][1] = to_tf32(p[8 * P_STRIDE] * 0.25f);
            qa[mt][ks][2] = to_tf32(p[4] * 0.25f);
            qa[mt][ks][3] = to_tf32(p[8 * P_STRIDE + 4] * 0.25f);
        }
    __syncwarp();

    float o[4][2][4];
    float lrow[4][2];
#pragma unroll
    for (int mt = 0; mt < 4; ++mt) {
        lrow[mt][0] = 0.f; lrow[mt][1] = 0.f;
#pragma unroll
        for (int nt = 0; nt < 2; ++nt)
#pragma unroll
            for (int r = 0; r < 4; ++r) o[mt][nt][r] = 0.f;
    }

    for (int j = 0; j < 16; ++j) {
        const int n0 = j * 32;
        uint32_t bk[4][2][2];
#pragma unroll
        for (int nt = 0; nt < 4; ++nt)
#pragma unroll
            for (int ks = 0; ks < 2; ++ks) {
                const uint32_t* p = Ks + (n0 + nt * 8 + g) * KS_STRIDE + ks * 8 + tig;
                bk[nt][ks][0] = p[0];
                bk[nt][ks][1] = p[4];
            }
        float c[4][4][4];
#pragma unroll
        for (int mt = 0; mt < 4; ++mt)
#pragma unroll
            for (int nt = 0; nt < 4; ++nt) {
#pragma unroll
                for (int r = 0; r < 4; ++r) c[mt][nt][r] = 0.f;
                mma_tf32(c[mt][nt], qa[mt][0], bk[nt][0]);
                mma_tf32(c[mt][nt], qa[mt][1], bk[nt][1]);
            }
#pragma unroll
        for (int mt = 0; mt < 4; ++mt) {
#pragma unroll
            for (int nt = 0; nt < 4; ++nt) {
                float p0 = __expf(c[mt][nt][0]);
                float p1 = __expf(c[mt][nt][1]);
                float p2 = __expf(c[mt][nt][2]);
                float p3 = __expf(c[mt][nt][3]);
                lrow[mt][0] += p0 + p1;
                lrow[mt][1] += p2 + p3;
                uint32_t* d0 = Pw + (mt * 16 + g) * P_STRIDE + nt * 8 + 2 * tig;
                uint32_t* d1 = d0 + 8 * P_STRIDE;
                d0[0] = to_tf32(p0); d0[1] = to_tf32(p1);
                d1[0] = to_tf32(p2); d1[1] = to_tf32(p3);
            }
        }
        __syncwarp();
        uint32_t bv[4][2][2];
#pragma unroll
        for (int k2 = 0; k2 < 4; ++k2)
#pragma unroll
            for (int nt = 0; nt < 2; ++nt) {
                const uint32_t* p = Vs + (n0 + k2 * 8 + tig) * VS_STRIDE + nt * 8 + g;
                bv[k2][nt][0] = p[0];
                bv[k2][nt][1] = p[4 * VS_STRIDE];
            }
#pragma unroll
        for (int mt = 0; mt < 4; ++mt) {
#pragma unroll
            for (int k2 = 0; k2 < 4; ++k2) {
                uint32_t pa[4];
                const uint32_t* pp = Pw + (mt * 16 + g) * P_STRIDE + k2 * 8 + tig;
                pa[0] = pp[0];
                pa[1] = pp[8 * P_STRIDE];
                pa[2] = pp[4];
                pa[3] = pp[8 * P_STRIDE + 4];
                mma_tf32(o[mt][0], pa, bv[k2][0]);
                mma_tf32(o[mt][1], pa, bv[k2][1]);
            }
        }
        __syncwarp();
    }

#pragma unroll
    for (int mt = 0; mt < 4; ++mt) {
        float l0 = lrow[mt][0], l1 = lrow[mt][1];
        l0 += __shfl_xor_sync(0xffffffffu, l0, 1);
        l0 += __shfl_xor_sync(0xffffffffu, l0, 2);
        l1 += __shfl_xor_sync(0xffffffffu, l1, 1);
        l1 += __shfl_xor_sync(0xffffffffu, l1, 2);
        float i0 = 1.f / l0, i1 = 1.f / l1;
        int grow = gi * SEQ + m0 + mt * 16 + g;
#pragma unroll
        for (int nt = 0; nt < 2; ++nt) {
            int col = h * 16 + nt * 8 + 2 * tig;
            *(float2*)(ao + (size_t)grow * DD + col) =
                make_float2(o[mt][nt][0] * i0, o[mt][nt][1] * i0);
            *(float2*)(ao + (size_t)(grow + 8) * DD + col) =
                make_float2(o[mt][nt][2] * i1, o[mt][nt][3] * i1);
        }
    }
}

// =====================================================================
// BatchNorm applies
// =====================================================================
__device__ __forceinline__ void bn_coef(const float* stats, const float* gamma,
                                        const float* beta, int col,
                                        float& sc, float& sh)
{
    float mean = stats[col] * (1.f / (float)NN);
    float var  = stats[128 + col] * (1.f / (float)NN) - mean * mean;
    sc = gamma[col] * rsqrtf(var + 1e-5f);
    sh = beta[col] - mean * sc;
}

__global__ void __launch_bounds__(256)
bn_apply_one(const float* __restrict__ X, const float* __restrict__ stats,
             const float* __restrict__ gamma, const float* __restrict__ beta,
             float* __restrict__ out)
{
    int col = threadIdx.x & 127;
    int half = threadIdx.x >> 7;
    float sc, sh;
    bn_coef(stats, gamma, beta, col, sc, sh);
    int row0 = blockIdx.x * 128 + half * 64;
    size_t off = (size_t)row0 * DD + col;
#pragma unroll 4
    for (int r = 0; r < 64; ++r)
        out[off + r * DD] = X[off + r * DD] * sc + sh;
}

__global__ void __launch_bounds__(256)
bn_apply_dual(const float* __restrict__ ha, const float* __restrict__ statsA,
              const float* __restrict__ ga, const float* __restrict__ ba,
              const float* __restrict__ hl, const float* __restrict__ statsL,
              const float* __restrict__ gl, const float* __restrict__ bl,
              float* __restrict__ out)
{
    int col = threadIdx.x & 127;
    int half = threadIdx.x >> 7;
    float scA, shA, scL, shL;
    bn_coef(statsA, ga, ba, col, scA, shA);
    bn_coef(statsL, gl, bl, col, scL, shL);
    int row0 = blockIdx.x * 128 + half * 64;
    size_t off = (size_t)row0 * DD + col;
#pragma unroll 4
    for (int r = 0; r < 64; ++r)
        out[off + r * DD] = ha[off + r * DD] * scA + shA
                          + hl[off + r * DD] * scL + shL;
}

// =====================================================================
// Host launcher
// =====================================================================
extern "C" void kernel_launch(void* const* d_in, const int* in_sizes, int n_in,
                              void* d_out, int out_size)
{
    const float* x          = (const float*)d_in[0];
    const int*   edge_index = (const int*)  d_in[1];
    const float* edge_attr  = (const float*)d_in[2];
    const float* gin_w1     = (const float*)d_in[3];
    const float* gin_b1     = (const float*)d_in[4];
    const float* gin_w2     = (const float*)d_in[5];
    const float* gin_b2     = (const float*)d_in[6];
    const float* bn1l_g     = (const float*)d_in[7];
    const float* bn1l_b     = (const float*)d_in[8];
    const float* in_proj_w  = (const float*)d_in[9];
    const float* in_proj_b  = (const float*)d_in[10];
    const float* out_proj_w = (const float*)d_in[11];
    const float* out_proj_b = (const float*)d_in[12];
    const float* bn1a_g     = (const float*)d_in[13];
    const float* bn1a_b     = (const float*)d_in[14];
    const float* ff_w1      = (const float*)d_in[15];
    const float* ff_b1      = (const float*)d_in[16];
    const float* ff_w2      = (const float*)d_in[17];
    const float* ff_b2      = (const float*)d_in[18];
    const float* bn2_g      = (const float*)d_in[19];
    const float* bn2_b      = (const float*)d_in[20];
    float* out = (float*)d_out;

    cudaFuncSetAttribute(attn_mma, cudaFuncAttributeMaxDynamicSharedMemorySize, ATTN_SMEM);
    cudaFuncSetAttribute(gemm_ar<false, false>, cudaFuncAttributeMaxDynamicSharedMemorySize, GEMM_AR_SMEM);
    cudaFuncSetAttribute(gemm_ar<true,  true >, cudaFuncAttributeMaxDynamicSharedMemorySize, GEMM_AR_SMEM);
    cudaFuncSetAttribute(mlp_fused<1, true>, cudaFuncAttributeMaxDynamicSharedMemorySize, MLP_SMEM);
    cudaFuncSetAttribute(mlp_fused<2, true>, cudaFuncAttributeMaxDynamicSharedMemorySize, MLP_SMEM);

    float *z, *hl, *qkvb, *ao, *ha, *h, *h2, *stats;
    int *deg, *off, *pos, *eid;
    cudaGetSymbolAddress((void**)&z,    g_z);
    cudaGetSymbolAddress((void**)&hl,   g_hl);
    cudaGetSymbolAddress((void**)&qkvb, g_qkv);
    cudaGetSymbolAddress((void**)&ao,   g_ao);
    cudaGetSymbolAddress((void**)&ha,   g_ha);
    cudaGetSymbolAddress((void**)&h,    g_h);
    cudaGetSymbolAddress((void**)&h2,   g_h2);
    cudaGetSymbolAddress((void**)&stats, g_stats);
    cudaGetSymbolAddress((void**)&deg,  g_deg);
    cudaGetSymbolAddress((void**)&off,  g_off);
    cudaGetSymbolAddress((void**)&pos,  g_pos);
    cudaGetSymbolAddress((void**)&eid,  g_eid);

    const int* src = edge_index;
    const int* dst = edge_index + EE;
    const dim3 blk(256);
    const int GB = NN / 128;

    float* stats_hl = stats;
    float* stats_ha = stats + 256;
    float* stats_h2 = stats + 512;

    // launch order puts attn_mma at profile index 3
    zero_misc<<<64, blk>>>(deg, stats);                                            // 0
    gemm_ar<false, false><<<dim3(GB, 3), blk, GEMM_AR_SMEM>>>(x, in_proj_w, in_proj_b,
                                                              nullptr, qkvb, 384, nullptr);  // 1: QKV
    count_kernel<<<EE / 256, blk>>>(dst, deg);                                     // 2
    attn_mma<<<NGR * NH, blk, ATTN_SMEM>>>(qkvb, ao);                              // 3  <- profiled
    scan_kernel<<<1, 1024>>>(deg, off, pos);                                       // 4
    scatter_kernel<<<EE / 256, blk>>>(dst, pos, eid);                              // 5
    aggr_kernel<<<NN / 8, blk>>>(x, src, edge_attr, off, eid, z);                  // 6
    mlp_fused<1, true><<<GB, blk, MLP_SMEM>>>(z, gin_w1, gin_b1, gin_w2, gin_b2,
                                              x, hl, stats_hl);                    // 7: GINE MLP
    gemm_ar<true, true><<<dim3(GB, 1), blk, GEMM_AR_SMEM>>>(ao, out_proj_w, out_proj_b,
                                                            x, ha, 128, stats_ha); // 8: out_proj
    bn_apply_dual<<<128, blk>>>(ha, stats_ha, bn1a_g, bn1a_b,
                                hl, stats_hl, bn1l_g, bn1l_b, h);                  // 9
    mlp_fused<2, true><<<GB, blk, MLP_SMEM>>>(h, ff_w1, ff_b1, ff_w2, ff_b2,
                                              h, h2, stats_h2);                    // 10: FFN
    bn_apply_one<<<128, blk>>>(h2, stats_h2, bn2_g, bn2_b, out);                   // 11
}

// round 6
// speedup vs baseline: 1.0500x; 1.0500x over previous
#include <cuda_runtime.h>
#include <math.h>
#include <stdint.h>

// Problem constants
constexpr int NN  = 16384;   // nodes
constexpr int DD  = 128;     // dim
constexpr int EE  = 262144;  // edges
constexpr int SEQ = 512;     // nodes per graph
constexpr int NGR = 32;      // graphs
constexpr int NH  = 8;       // heads (dh = 16)

// ---------------- scratch ----------------
__device__ float g_z   [NN * DD];
__device__ float g_hl  [NN * DD];
__device__ float g_qkv [NN * 3 * DD];
__device__ float g_ao  [NN * DD];
__device__ float g_ha  [NN * DD];
__device__ float g_h   [NN * DD];
__device__ float g_h2  [NN * DD];
__device__ float g_stats[768];   // [0:256) hl, [256:512) ha, [512:768) h2
__device__ int   g_deg [NN];
__device__ int   g_off [NN + 1];
__device__ int   g_pos [NN];
__device__ int   g_eid [EE];

// =====================================================================
__global__ void zero_misc(int* deg, float* stats)
{
    int i = blockIdx.x * 256 + threadIdx.x;
    deg[i] = 0;
    if (i < 768) stats[i] = 0.f;
}

// =====================================================================
// CSR build by dst:  count -> scan -> scatter
// =====================================================================
__global__ void count_kernel(const int* __restrict__ dst, int* __restrict__ deg)
{
    int e = blockIdx.x * 256 + threadIdx.x;
    atomicAdd(&deg[dst[e]], 1);
}

__global__ void __launch_bounds__(1024)
scan_kernel(const int* __restrict__ deg, int* __restrict__ off, int* __restrict__ pos)
{
    __shared__ int buf[2][1024];
    int t = threadIdx.x;
    int base = t * 16;
    int loc[16];
    int sum = 0;
#pragma unroll
    for (int i = 0; i < 16; ++i) { loc[i] = sum; sum += deg[base + i]; }
    buf[0][t] = sum;
    __syncthreads();
    int sel = 0;
    for (int d = 1; d < 1024; d <<= 1) {
        int v = buf[sel][t] + (t >= d ? buf[sel][t - d] : 0);
        buf[sel ^ 1][t] = v;
        sel ^= 1;
        __syncthreads();
    }
    int excl = buf[sel][t] - sum;
#pragma unroll
    for (int i = 0; i < 16; ++i) {
        int o = excl + loc[i];
        off[base + i] = o;
        pos[base + i] = o;
    }
    if (t == 1023) off[NN] = excl + sum;
}

__global__ void scatter_kernel(const int* __restrict__ dst, int* __restrict__ pos,
                               int* __restrict__ eid)
{
    int e = blockIdx.x * 256 + threadIdx.x;
    int p = atomicAdd(&pos[dst[e]], 1);
    eid[p] = e;
}

// =====================================================================
// Gather aggregation: z = x + sum_{e -> node} relu(x[src[e]] + ea[e])
// =====================================================================
__global__ void __launch_bounds__(256)
aggr_kernel(const float* __restrict__ x, const int* __restrict__ src,
            const float* __restrict__ ea, const int* __restrict__ off,
            const int* __restrict__ eid, float* __restrict__ z)
{
    int node = blockIdx.x * 8 + (threadIdx.x >> 5);
    int lane = threadIdx.x & 31;
    int beg = off[node], end = off[node + 1];
    const float4* x4  = (const float4*)x;
    const float4* ea4 = (const float4*)ea;
    float4 acc = make_float4(0.f, 0.f, 0.f, 0.f);
#pragma unroll 2
    for (int i = beg; i < end; ++i) {
        int e = __ldg(eid + i);
        int s = __ldg(src + e);
        float4 a = x4[(size_t)s * 32 + lane];
        float4 b = ea4[(size_t)e * 32 + lane];
        acc.x += fmaxf(a.x + b.x, 0.f);
        acc.y += fmaxf(a.y + b.y, 0.f);
        acc.z += fmaxf(a.z + b.z, 0.f);
        acc.w += fmaxf(a.w + b.w, 0.f);
    }
    float4 xv = x4[(size_t)node * 32 + lane];
    ((float4*)z)[(size_t)node * 32 + lane] =
        make_float4(xv.x + acc.x, xv.y + acc.y, xv.z + acc.z, xv.w + acc.w);
}

// =====================================================================
// TF32 mma helpers
// =====================================================================
__device__ __forceinline__ uint32_t to_tf32(float f)
{
    uint32_t u;
    asm("cvt.rna.tf32.f32 %0, %1;" : "=r"(u) : "f"(f));
    return u;
}

__device__ __forceinline__ void mma_tf32(float c[4], const uint32_t a[4], const uint32_t b[2])
{
    asm volatile(
        "mma.sync.aligned.m16n8k8.row.col.f32.tf32.tf32.f32 "
        "{%0,%1,%2,%3}, {%4,%5,%6,%7}, {%8,%9}, {%0,%1,%2,%3};\n"
        : "+f"(c[0]), "+f"(c[1]), "+f"(c[2]), "+f"(c[3])
        : "r"(a[0]), "r"(a[1]), "r"(a[2]), "r"(a[3]), "r"(b[0]), "r"(b[1]));
}

constexpr int AST = 132;   // A/T smem stride (u32)
constexpr int BST = 20;    // B-chunk smem stride

// one 16-k-slab of mma: A-src (stride AST), B-chunk (stride BST)
__device__ __forceinline__ void mma_slab16(const uint32_t* S, const uint32_t* Bb,
                                           float acc[4][4][4],
                                           int wm, int wn, int g, int tig, int kt)
{
#pragma unroll
    for (int k8s = 0; k8s < 2; ++k8s) {
        const int kk = kt * 16 + k8s * 8;
        uint32_t af[4][4];
#pragma unroll
        for (int mf = 0; mf < 4; ++mf) {
            const uint32_t* pa = S + (wm * 64 + mf * 16 + g) * AST + kk + tig;
            af[mf][0] = pa[0];
            af[mf][1] = pa[8 * AST];
            af[mf][2] = pa[4];
            af[mf][3] = pa[8 * AST + 4];
        }
        uint32_t bf[4][2];
#pragma unroll
        for (int nf = 0; nf < 4; ++nf) {
            const uint32_t* pb = Bb + (wn * 32 + nf * 8 + g) * BST + k8s * 8 + tig;
            bf[nf][0] = pb[0];
            bf[nf][1] = pb[4];
        }
#pragma unroll
        for (int mf = 0; mf < 4; ++mf)
#pragma unroll
            for (int nf = 0; nf < 4; ++nf)
                mma_tf32(acc[mf][nf], af[mf], bf[nf]);
    }
}

// epilogue shared by gemm_ar / mlp_fused
template<bool RELU, bool RESID, bool STATS>
__device__ __forceinline__ void gemm_epilogue(
    float acc[4][4][4], const float* bias, const float* resid,
    float* C, int ldc, int m0, int n0,
    int wm, int wn, int g, int tig, int tid,
    float* stats, float* sst /* 256-float smem scratch */)
{
    float cs[8], cq[8];
    if (STATS) {
#pragma unroll
        for (int j = 0; j < 8; ++j) { cs[j] = 0.f; cq[j] = 0.f; }
    }
#pragma unroll
    for (int mf = 0; mf < 4; ++mf) {
#pragma unroll
        for (int nf = 0; nf < 4; ++nf) {
            int row = m0 + wm * 64 + mf * 16 + g;
            int col = n0 + wn * 32 + nf * 8 + 2 * tig;
            float b0 = bias[col], b1 = bias[col + 1];
            float o00 = acc[mf][nf][0] + b0, o01 = acc[mf][nf][1] + b1;
            float o10 = acc[mf][nf][2] + b0, o11 = acc[mf][nf][3] + b1;
            if (RELU) {
                o00 = fmaxf(o00, 0.f); o01 = fmaxf(o01, 0.f);
                o10 = fmaxf(o10, 0.f); o11 = fmaxf(o11, 0.f);
            }
            if (RESID) {
                float2 r0 = *(const float2*)(resid + (size_t)row * ldc + col);
                float2 r1 = *(const float2*)(resid + (size_t)(row + 8) * ldc + col);
                o00 += r0.x; o01 += r0.y;
                o10 += r1.x; o11 += r1.y;
            }
            if (STATS) {
                cs[nf*2]   += o00 + o10;
                cs[nf*2+1] += o01 + o11;
                cq[nf*2]   += o00*o00 + o10*o10;
                cq[nf*2+1] += o01*o01 + o11*o11;
            }
            *(float2*)(C + (size_t)row * ldc + col)       = make_float2(o00, o01);
            *(float2*)(C + (size_t)(row + 8) * ldc + col) = make_float2(o10, o11);
        }
    }
    if (STATS) {
        __syncthreads();
        sst[tid] = 0.f;
        __syncthreads();
#pragma unroll
        for (int j = 0; j < 8; ++j) {
            int col = wn * 32 + (j >> 1) * 8 + 2 * tig + (j & 1);
            atomicAdd(&sst[col],       cs[j]);
            atomicAdd(&sst[128 + col], cq[j]);
        }
        __syncthreads();
        atomicAdd(&stats[tid], sst[tid]);
    }
}

// =====================================================================
// A-resident GEMM (K=128): C = A[128rows,128] @ B^T + bias (+resid)(+stats)
// =====================================================================
constexpr int GEMM_AR_SMEM = (128 * AST + 128 * BST) * 4;

template<bool RESID, bool STATS>
__global__ void __launch_bounds__(256, 2)
gemm_ar(const float* __restrict__ A,
        const float* __restrict__ B,
        const float* __restrict__ bias,
        const float* __restrict__ resid,
        float* __restrict__ C, int ldc,
        float* __restrict__ stats)
{
    extern __shared__ uint32_t sm[];
    uint32_t* Abuf = sm;               // [128][AST]
    uint32_t* Bbuf = sm + 128 * AST;   // [128][BST]

    const int tid = threadIdx.x;
    const int lane = tid & 31, warp = tid >> 5;
    const int wm = warp >> 2, wn = warp & 3;
    const int g = lane >> 2, tig = lane & 3;
    const int m0 = blockIdx.x * 128;
    const int n0 = blockIdx.y * 128;

#pragma unroll
    for (int it = 0; it < 16; ++it) {
        int idx = tid + it * 256;
        int r = idx >> 5, c4 = (idx & 31) * 4;
        float4 v = *(const float4*)(A + (size_t)(m0 + r) * 128 + c4);
        uint32_t* d = Abuf + r * AST + c4;
        d[0] = to_tf32(v.x); d[1] = to_tf32(v.y);
        d[2] = to_tf32(v.z); d[3] = to_tf32(v.w);
    }

    float acc[4][4][4];
#pragma unroll
    for (int i = 0; i < 4; ++i)
#pragma unroll
        for (int j = 0; j < 4; ++j)
#pragma unroll
            for (int r = 0; r < 4; ++r) acc[i][j][r] = 0.f;

    float4 pre0, pre1;
    {
        int i0 = tid, i1 = tid + 256;
        pre0 = *(const float4*)(B + (size_t)(n0 + (i0 >> 2)) * 128 + (i0 & 3) * 4);
        pre1 = *(const float4*)(B + (size_t)(n0 + (i1 >> 2)) * 128 + (i1 & 3) * 4);
    }

    for (int kt = 0; kt < 8; ++kt) {
        __syncthreads();
        {
            int i0 = tid, i1 = tid + 256;
            uint32_t* d0 = Bbuf + (i0 >> 2) * BST + (i0 & 3) * 4;
            d0[0] = to_tf32(pre0.x); d0[1] = to_tf32(pre0.y);
            d0[2] = to_tf32(pre0.z); d0[3] = to_tf32(pre0.w);
            uint32_t* d1 = Bbuf + (i1 >> 2) * BST + (i1 & 3) * 4;
            d1[0] = to_tf32(pre1.x); d1[1] = to_tf32(pre1.y);
            d1[2] = to_tf32(pre1.z); d1[3] = to_tf32(pre1.w);
        }
        if (kt < 7) {
            int i0 = tid, i1 = tid + 256;
            pre0 = *(const float4*)(B + (size_t)(n0 + (i0 >> 2)) * 128 + (kt + 1) * 16 + (i0 & 3) * 4);
            pre1 = *(const float4*)(B + (size_t)(n0 + (i1 >> 2)) * 128 + (kt + 1) * 16 + (i1 & 3) * 4);
        }
        __syncthreads();
        mma_slab16(Abuf, Bbuf, acc, wm, wn, g, tig, kt);
    }

    gemm_epilogue<false, RESID, STATS>(acc, bias, resid, C, ldc, m0, n0,
                                       wm, wn, g, tig, tid, stats, (float*)Bbuf);
}

// =====================================================================
// Fused MLP: C = relu(A @ W1 + b1) @ W2 + b2 (+resid)(+stats)
// =====================================================================
constexpr int MLP_SMEM = (2 * 128 * AST + 128 * BST) * 4;

template<int NC, bool STATS>
__global__ void __launch_bounds__(256, 1)
mlp_fused(const float* __restrict__ A,
          const float* __restrict__ W1, const float* __restrict__ b1,
          const float* __restrict__ W2, const float* __restrict__ b2,
          const float* __restrict__ resid,
          float* __restrict__ C,
          float* __restrict__ stats)
{
    extern __shared__ uint32_t sm[];
    uint32_t* Abuf = sm;                   // [128][AST]
    uint32_t* Tbuf = sm + 128 * AST;       // [128][AST]
    uint32_t* Bbuf = sm + 2 * 128 * AST;   // [128][BST]

    const int tid = threadIdx.x;
    const int lane = tid & 31, warp = tid >> 5;
    const int wm = warp >> 2, wn = warp & 3;
    const int g = lane >> 2, tig = lane & 3;
    const int m0 = blockIdx.x * 128;
    const int ldw1 = NC * 128;

#pragma unroll
    for (int it = 0; it < 16; ++it) {
        int idx = tid + it * 256;
        int r = idx >> 5, c4 = (idx & 31) * 4;
        float4 v = *(const float4*)(A + (size_t)(m0 + r) * 128 + c4);
        uint32_t* d = Abuf + r * AST + c4;
        d[0] = to_tf32(v.x); d[1] = to_tf32(v.y);
        d[2] = to_tf32(v.z); d[3] = to_tf32(v.w);
    }

    float co[4][4][4];
#pragma unroll
    for (int i = 0; i < 4; ++i)
#pragma unroll
        for (int j = 0; j < 4; ++j)
#pragma unroll
            for (int r = 0; r < 4; ++r) co[i][j][r] = 0.f;

    const int kk = tid >> 7;        // 0..1
    const int nn2 = tid & 127;      // n col

#pragma unroll
    for (int nc = 0; nc < NC; ++nc) {
        float c1[4][4][4];
#pragma unroll
        for (int i = 0; i < 4; ++i)
#pragma unroll
            for (int j = 0; j < 4; ++j)
#pragma unroll
                for (int r = 0; r < 4; ++r) c1[i][j][r] = 0.f;

        float pre[8];
#pragma unroll
        for (int j = 0; j < 8; ++j)
            pre[j] = W1[(size_t)(j * 2 + kk) * ldw1 + nc * 128 + nn2];

        for (int kt = 0; kt < 8; ++kt) {
            __syncthreads();
#pragma unroll
            for (int j = 0; j < 8; ++j)
                Bbuf[nn2 * BST + j * 2 + kk] = to_tf32(pre[j]);
            if (kt < 7) {
#pragma unroll
                for (int j = 0; j < 8; ++j)
                    pre[j] = W1[(size_t)((kt + 1) * 16 + j * 2 + kk) * ldw1 + nc * 128 + nn2];
            }
            __syncthreads();
            mma_slab16(Abuf, Bbuf, c1, wm, wn, g, tig, kt);
        }

#pragma unroll
        for (int mf = 0; mf < 4; ++mf) {
#pragma unroll
            for (int nf = 0; nf < 4; ++nf) {
                int row = wm * 64 + mf * 16 + g;
                int col = wn * 32 + nf * 8 + 2 * tig;
                float bb0 = b1[nc * 128 + col], bb1 = b1[nc * 128 + col + 1];
                Tbuf[row * AST + col]           = to_tf32(fmaxf(c1[mf][nf][0] + bb0, 0.f));
                Tbuf[row * AST + col + 1]       = to_tf32(fmaxf(c1[mf][nf][1] + bb1, 0.f));
                Tbuf[(row + 8) * AST + col]     = to_tf32(fmaxf(c1[mf][nf][2] + bb0, 0.f));
                Tbuf[(row + 8) * AST + col + 1] = to_tf32(fmaxf(c1[mf][nf][3] + bb1, 0.f));
            }
        }

#pragma unroll
        for (int j = 0; j < 8; ++j)
            pre[j] = W2[(size_t)(nc * 128 + j * 2 + kk) * 128 + nn2];

        for (int kt = 0; kt < 8; ++kt) {
            __syncthreads();
#pragma unroll
            for (int j = 0; j < 8; ++j)
                Bbuf[nn2 * BST + j * 2 + kk] = to_tf32(pre[j]);
            if (kt < 7) {
#pragma unroll
                for (int j = 0; j < 8; ++j)
                    pre[j] = W2[(size_t)(nc * 128 + (kt + 1) * 16 + j * 2 + kk) * 128 + nn2];
            }
            __syncthreads();
            mma_slab16(Tbuf, Bbuf, co, wm, wn, g, tig, kt);
        }
    }

    gemm_epilogue<false, true, STATS>(co, b2, resid, C, 128, m0, 0,
                                      wm, wn, g, tig, tid, stats, (float*)Bbuf);
}

// =====================================================================
// Flash-style TF32 attention, v2: shuffle-transposed P (no P smem),
// 32 q-rows/warp, block = (graph, head, half), occupancy 2.
// =====================================================================
constexpr int KS_STRIDE = 20;
constexpr int VS_STRIDE = 24;
constexpr int ATTN_SMEM = (512 * KS_STRIDE + 512 * VS_STRIDE) * 4;   // 88KB

__global__ void __launch_bounds__(256, 2)
attn_mma(const float* __restrict__ qkv, float* __restrict__ ao)
{
    extern __shared__ uint32_t sm[];
    uint32_t* Ks = sm;                    // [512][20] tf32
    uint32_t* Vs = sm + 512 * KS_STRIDE;  // [512][24] tf32

    const int tid  = threadIdx.x;
    const int lane = tid & 31;
    const int warp = tid >> 5;
    const int g    = lane >> 2;   // 0..7
    const int tig  = lane & 3;    // 0..3
    const int b    = blockIdx.x;
    const int gi = b >> 4, h = (b >> 1) & 7, half = b & 1;
    const float* base = qkv + (size_t)gi * SEQ * 384;
    const int m0 = half * 256 + warp * 32;

    // ---- stage K, V (tf32, padded) ----
    for (int idx = tid; idx < 2048; idx += 256) {
        int r = idx >> 2, c4 = (idx & 3) * 4;
        float4 kv = *(const float4*)(base + (size_t)r * 384 + 128 + h * 16 + c4);
        float4 vv = *(const float4*)(base + (size_t)r * 384 + 256 + h * 16 + c4);
        uint32_t* kd = Ks + r * KS_STRIDE + c4;
        kd[0] = to_tf32(kv.x); kd[1] = to_tf32(kv.y);
        kd[2] = to_tf32(kv.z); kd[3] = to_tf32(kv.w);
        uint32_t* vd = Vs + r * VS_STRIDE + c4;
        vd[0] = to_tf32(vv.x); vd[1] = to_tf32(vv.y);
        vd[2] = to_tf32(vv.z); vd[3] = to_tf32(vv.w);
    }

    // ---- Q fragments straight from gmem (scale 1/sqrt(dh)=0.25 folded) ----
    uint32_t qa[2][2][4];
#pragma unroll
    for (int mt = 0; mt < 2; ++mt)
#pragma unroll
        for (int ks = 0; ks < 2; ++ks) {
            const float* p = base + (size_t)(m0 + mt * 16 + g) * 384 + h * 16 + ks * 8 + tig;
            qa[mt][ks][0] = to_tf32(p[0] * 0.25f);
            qa[mt][ks][1] = to_tf32(p[8 * 384] * 0.25f);
            qa[mt][ks][2] = to_tf32(p[4] * 0.25f);
            qa[mt][ks][3] = to_tf32(p[8 * 384 + 4] * 0.25f);
        }
    __syncthreads();

    const int sidx  = g * 4 + (tig >> 1);   // shuffle src for cols tig
    const int sidx2 = sidx + 2;             // shuffle src for cols tig+4
    const bool odd  = (tig & 1);

    float o[2][2][4];
    float lrow[2][2];
#pragma unroll
    for (int mt = 0; mt < 2; ++mt) {
        lrow[mt][0] = 0.f; lrow[mt][1] = 0.f;
#pragma unroll
        for (int nt = 0; nt < 2; ++nt)
#pragma unroll
            for (int r = 0; r < 4; ++r) o[mt][nt][r] = 0.f;
    }

    for (int j = 0; j < 16; ++j) {      // kv chunk of 32
        const int n0 = j * 32;
        uint32_t pa[2][4][4];           // [mt][k2][reg] — P in a-frag layout

#pragma unroll
        for (int nt = 0; nt < 4; ++nt) {
            // K b-frags for this 8-kv column group
            uint32_t bk[2][2];
#pragma unroll
            for (int ks = 0; ks < 2; ++ks) {
                const uint32_t* p = Ks + (n0 + nt * 8 + g) * KS_STRIDE + ks * 8 + tig;
                bk[ks][0] = p[0];
                bk[ks][1] = p[4];
            }
#pragma unroll
            for (int mt = 0; mt < 2; ++mt) {
                float c[4] = {0.f, 0.f, 0.f, 0.f};
                mma_tf32(c, qa[mt][0], bk[0]);
                mma_tf32(c, qa[mt][1], bk[1]);
                float p0 = __expf(c[0]);
                float p1 = __expf(c[1]);
                float p2 = __expf(c[2]);
                float p3 = __expf(c[3]);
                lrow[mt][0] += p0 + p1;
                lrow[mt][1] += p2 + p3;
                // c-layout -> a-layout via shuffles:
                // a0 = P[g][tig], a1 = P[g+8][tig], a2 = P[g][tig+4], a3 = P[g+8][tig+4]
                float s0 = __shfl_sync(0xffffffffu, p0, sidx);
                float s1 = __shfl_sync(0xffffffffu, p1, sidx);
                float u0 = __shfl_sync(0xffffffffu, p2, sidx);
                float u1 = __shfl_sync(0xffffffffu, p3, sidx);
                float t0 = __shfl_sync(0xffffffffu, p0, sidx2);
                float t1 = __shfl_sync(0xffffffffu, p1, sidx2);
                float v0 = __shfl_sync(0xffffffffu, p2, sidx2);
                float v1 = __shfl_sync(0xffffffffu, p3, sidx2);
                pa[mt][nt][0] = to_tf32(odd ? s1 : s0);
                pa[mt][nt][1] = to_tf32(odd ? u1 : u0);
                pa[mt][nt][2] = to_tf32(odd ? t1 : t0);
                pa[mt][nt][3] = to_tf32(odd ? v1 : v0);
            }
        }

        // O += P @ V
#pragma unroll
        for (int k2 = 0; k2 < 4; ++k2) {
            uint32_t bv[2][2];
#pragma unroll
            for (int nt = 0; nt < 2; ++nt) {
                const uint32_t* p = Vs + (n0 + k2 * 8 + tig) * VS_STRIDE + nt * 8 + g;
                bv[nt][0] = p[0];
                bv[nt][1] = p[4 * VS_STRIDE];
            }
#pragma unroll
            for (int mt = 0; mt < 2; ++mt) {
                mma_tf32(o[mt][0], pa[mt][k2], bv[0]);
                mma_tf32(o[mt][1], pa[mt][k2], bv[1]);
            }
        }
    }

    // ---- normalize + write ----
#pragma unroll
    for (int mt = 0; mt < 2; ++mt) {
        float l0 = lrow[mt][0], l1 = lrow[mt][1];
        l0 += __shfl_xor_sync(0xffffffffu, l0, 1);
        l0 += __shfl_xor_sync(0xffffffffu, l0, 2);
        l1 += __shfl_xor_sync(0xffffffffu, l1, 1);
        l1 += __shfl_xor_sync(0xffffffffu, l1, 2);
        float i0 = 1.f / l0, i1 = 1.f / l1;
        int grow = gi * SEQ + m0 + mt * 16 + g;
#pragma unroll
        for (int nt = 0; nt < 2; ++nt) {
            int col = h * 16 + nt * 8 + 2 * tig;
            *(float2*)(ao + (size_t)grow * DD + col) =
                make_float2(o[mt][nt][0] * i0, o[mt][nt][1] * i0);
            *(float2*)(ao + (size_t)(grow + 8) * DD + col) =
                make_float2(o[mt][nt][2] * i1, o[mt][nt][3] * i1);
        }
    }
}

// =====================================================================
// BatchNorm applies
// =====================================================================
__device__ __forceinline__ void bn_coef(const float* stats, const float* gamma,
                                        const float* beta, int col,
                                        float& sc, float& sh)
{
    float mean = stats[col] * (1.f / (float)NN);
    float var  = stats[128 + col] * (1.f / (float)NN) - mean * mean;
    sc = gamma[col] * rsqrtf(var + 1e-5f);
    sh = beta[col] - mean * sc;
}

__global__ void __launch_bounds__(256)
bn_apply_one(const float* __restrict__ X, const float* __restrict__ stats,
             const float* __restrict__ gamma, const float* __restrict__ beta,
             float* __restrict__ out)
{
    int col = threadIdx.x & 127;
    int half = threadIdx.x >> 7;
    float sc, sh;
    bn_coef(stats, gamma, beta, col, sc, sh);
    int row0 = blockIdx.x * 128 + half * 64;
    size_t off = (size_t)row0 * DD + col;
#pragma unroll 4
    for (int r = 0; r < 64; ++r)
        out[off + r * DD] = X[off + r * DD] * sc + sh;
}

__global__ void __launch_bounds__(256)
bn_apply_dual(const float* __restrict__ ha, const float* __restrict__ statsA,
              const float* __restrict__ ga, const float* __restrict__ ba,
              const float* __restrict__ hl, const float* __restrict__ statsL,
              const float* __restrict__ gl, const float* __restrict__ bl,
              float* __restrict__ out)
{
    int col = threadIdx.x & 127;
    int half = threadIdx.x >> 7;
    float scA, shA, scL, shL;
    bn_coef(statsA, ga, ba, col, scA, shA);
    bn_coef(statsL, gl, bl, col, scL, shL);
    int row0 = blockIdx.x * 128 + half * 64;
    size_t off = (size_t)row0 * DD + col;
#pragma unroll 4
    for (int r = 0; r < 64; ++r)
        out[off + r * DD] = ha[off + r * DD] * scA + shA
                          + hl[off + r * DD] * scL + shL;
}

// =====================================================================
// Host launcher
// =====================================================================
extern "C" void kernel_launch(void* const* d_in, const int* in_sizes, int n_in,
                              void* d_out, int out_size)
{
    const float* x          = (const float*)d_in[0];
    const int*   edge_index = (const int*)  d_in[1];
    const float* edge_attr  = (const float*)d_in[2];
    const float* gin_w1     = (const float*)d_in[3];
    const float* gin_b1     = (const float*)d_in[4];
    const float* gin_w2     = (const float*)d_in[5];
    const float* gin_b2     = (const float*)d_in[6];
    const float* bn1l_g     = (const float*)d_in[7];
    const float* bn1l_b     = (const float*)d_in[8];
    const float* in_proj_w  = (const float*)d_in[9];
    const float* in_proj_b  = (const float*)d_in[10];
    const float* out_proj_w = (const float*)d_in[11];
    const float* out_proj_b = (const float*)d_in[12];
    const float* bn1a_g     = (const float*)d_in[13];
    const float* bn1a_b     = (const float*)d_in[14];
    const float* ff_w1      = (const float*)d_in[15];
    const float* ff_b1      = (const float*)d_in[16];
    const float* ff_w2      = (const float*)d_in[17];
    const float* ff_b2      = (const float*)d_in[18];
    const float* bn2_g      = (const float*)d_in[19];
    const float* bn2_b      = (const float*)d_in[20];
    float* out = (float*)d_out;

    cudaFuncSetAttribute(attn_mma, cudaFuncAttributeMaxDynamicSharedMemorySize, ATTN_SMEM);
    cudaFuncSetAttribute(gemm_ar<false, false>, cudaFuncAttributeMaxDynamicSharedMemorySize, GEMM_AR_SMEM);
    cudaFuncSetAttribute(gemm_ar<true,  true >, cudaFuncAttributeMaxDynamicSharedMemorySize, GEMM_AR_SMEM);
    cudaFuncSetAttribute(mlp_fused<1, true>, cudaFuncAttributeMaxDynamicSharedMemorySize, MLP_SMEM);
    cudaFuncSetAttribute(mlp_fused<2, true>, cudaFuncAttributeMaxDynamicSharedMemorySize, MLP_SMEM);

    float *z, *hl, *qkvb, *ao, *ha, *h, *h2, *stats;
    int *deg, *off, *pos, *eid;
    cudaGetSymbolAddress((void**)&z,    g_z);
    cudaGetSymbolAddress((void**)&hl,   g_hl);
    cudaGetSymbolAddress((void**)&qkvb, g_qkv);
    cudaGetSymbolAddress((void**)&ao,   g_ao);
    cudaGetSymbolAddress((void**)&ha,   g_ha);
    cudaGetSymbolAddress((void**)&h,    g_h);
    cudaGetSymbolAddress((void**)&h2,   g_h2);
    cudaGetSymbolAddress((void**)&stats, g_stats);
    cudaGetSymbolAddress((void**)&deg,  g_deg);
    cudaGetSymbolAddress((void**)&off,  g_off);
    cudaGetSymbolAddress((void**)&pos,  g_pos);
    cudaGetSymbolAddress((void**)&eid,  g_eid);

    const int* src = edge_index;
    const int* dst = edge_index + EE;
    const dim3 blk(256);
    const int GB = NN / 128;

    float* stats_hl = stats;
    float* stats_ha = stats + 256;
    float* stats_h2 = stats + 512;

    // launch order keeps attn_mma at profile index 3
    zero_misc<<<64, blk>>>(deg, stats);                                            // 0
    gemm_ar<false, false><<<dim3(GB, 3), blk, GEMM_AR_SMEM>>>(x, in_proj_w, in_proj_b,
                                                              nullptr, qkvb, 384, nullptr);  // 1: QKV
    count_kernel<<<EE / 256, blk>>>(dst, deg);                                     // 2
    attn_mma<<<NGR * NH * 2, blk, ATTN_SMEM>>>(qkvb, ao);                          // 3  <- profiled
    scan_kernel<<<1, 1024>>>(deg, off, pos);                                       // 4
    scatter_kernel<<<EE / 256, blk>>>(dst, pos, eid);                              // 5
    aggr_kernel<<<NN / 8, blk>>>(x, src, edge_attr, off, eid, z);                  // 6
    mlp_fused<1, true><<<GB, blk, MLP_SMEM>>>(z, gin_w1, gin_b1, gin_w2, gin_b2,
                                              x, hl, stats_hl);                    // 7: GINE MLP
    gemm_ar<true, true><<<dim3(GB, 1), blk, GEMM_AR_SMEM>>>(ao, out_proj_w, out_proj_b,
                                                            x, ha, 128, stats_ha); // 8: out_proj
    bn_apply_dual<<<128, blk>>>(ha, stats_ha, bn1a_g, bn1a_b,
                                hl, stats_hl, bn1l_g, bn1l_b, h);                  // 9
    mlp_fused<2, true><<<GB, blk, MLP_SMEM>>>(h, ff_w1, ff_b1, ff_w2, ff_b2,
                                              h, h2, stats_h2);                    // 10: FFN
    bn_apply_one<<<128, blk>>>(h2, stats_h2, bn2_g, bn2_b, out);                   // 11
}

// round 7
// speedup vs baseline: 1.1471x; 1.0925x over previous
#include <cuda_runtime.h>
#include <cuda_bf16.h>
#include <math.h>
#include <stdint.h>

// Problem constants
constexpr int NN  = 16384;   // nodes
constexpr int DD  = 128;     // dim
constexpr int EE  = 262144;  // edges
constexpr int SEQ = 512;     // nodes per graph
constexpr int NGR = 32;      // graphs
constexpr int NH  = 8;       // heads (dh = 16)

// ---------------- scratch ----------------
__device__ float g_z   [NN * DD];
__device__ float g_hl  [NN * DD];
__device__ float g_qkv [NN * 3 * DD];
__device__ float g_ao  [NN * DD];
__device__ float g_ha  [NN * DD];
__device__ float g_h   [NN * DD];
__device__ float g_h2  [NN * DD];
__device__ float g_stats[768];   // [0:256) hl, [256:512) ha, [512:768) h2
__device__ int   g_deg [NN];
__device__ int   g_off [NN + 1];
__device__ int   g_pos [NN];
__device__ int   g_eid [EE];

// =====================================================================
__global__ void zero_misc(int* deg, float* stats)
{
    int i = blockIdx.x * 256 + threadIdx.x;
    deg[i] = 0;
    if (i < 768) stats[i] = 0.f;
}

// =====================================================================
// CSR build by dst:  count -> scan -> scatter
// =====================================================================
__global__ void count_kernel(const int* __restrict__ dst, int* __restrict__ deg)
{
    int e = blockIdx.x * 256 + threadIdx.x;
    atomicAdd(&deg[dst[e]], 1);
}

__global__ void __launch_bounds__(1024)
scan_kernel(const int* __restrict__ deg, int* __restrict__ off, int* __restrict__ pos)
{
    __shared__ int buf[2][1024];
    int t = threadIdx.x;
    int base = t * 16;
    int loc[16];
    int sum = 0;
#pragma unroll
    for (int i = 0; i < 16; ++i) { loc[i] = sum; sum += deg[base + i]; }
    buf[0][t] = sum;
    __syncthreads();
    int sel = 0;
    for (int d = 1; d < 1024; d <<= 1) {
        int v = buf[sel][t] + (t >= d ? buf[sel][t - d] : 0);
        buf[sel ^ 1][t] = v;
        sel ^= 1;
        __syncthreads();
    }
    int excl = buf[sel][t] - sum;
#pragma unroll
    for (int i = 0; i < 16; ++i) {
        int o = excl + loc[i];
        off[base + i] = o;
        pos[base + i] = o;
    }
    if (t == 1023) off[NN] = excl + sum;
}

__global__ void scatter_kernel(const int* __restrict__ dst, int* __restrict__ pos,
                               int* __restrict__ eid)
{
    int e = blockIdx.x * 256 + threadIdx.x;
    int p = atomicAdd(&pos[dst[e]], 1);
    eid[p] = e;
}

// =====================================================================
// Gather aggregation: z = x + sum_{e -> node} relu(x[src[e]] + ea[e])
// =====================================================================
__global__ void __launch_bounds__(256)
aggr_kernel(const float* __restrict__ x, const int* __restrict__ src,
            const float* __restrict__ ea, const int* __restrict__ off,
            const int* __restrict__ eid, float* __restrict__ z)
{
    int node = blockIdx.x * 8 + (threadIdx.x >> 5);
    int lane = threadIdx.x & 31;
    int beg = off[node], end = off[node + 1];
    const float4* x4  = (const float4*)x;
    const float4* ea4 = (const float4*)ea;
    float4 acc = make_float4(0.f, 0.f, 0.f, 0.f);
#pragma unroll 2
    for (int i = beg; i < end; ++i) {
        int e = __ldg(eid + i);
        int s = __ldg(src + e);
        float4 a = x4[(size_t)s * 32 + lane];
        float4 b = ea4[(size_t)e * 32 + lane];
        acc.x += fmaxf(a.x + b.x, 0.f);
        acc.y += fmaxf(a.y + b.y, 0.f);
        acc.z += fmaxf(a.z + b.z, 0.f);
        acc.w += fmaxf(a.w + b.w, 0.f);
    }
    float4 xv = x4[(size_t)node * 32 + lane];
    ((float4*)z)[(size_t)node * 32 + lane] =
        make_float4(xv.x + acc.x, xv.y + acc.y, xv.z + acc.z, xv.w + acc.w);
}

// =====================================================================
// mma helpers
// =====================================================================
__device__ __forceinline__ uint32_t to_tf32(float f)
{
    uint32_t u;
    asm("cvt.rna.tf32.f32 %0, %1;" : "=r"(u) : "f"(f));
    return u;
}

__device__ __forceinline__ void mma_tf32(float c[4], const uint32_t a[4], const uint32_t b[2])
{
    asm volatile(
        "mma.sync.aligned.m16n8k8.row.col.f32.tf32.tf32.f32 "
        "{%0,%1,%2,%3}, {%4,%5,%6,%7}, {%8,%9}, {%0,%1,%2,%3};\n"
        : "+f"(c[0]), "+f"(c[1]), "+f"(c[2]), "+f"(c[3])
        : "r"(a[0]), "r"(a[1]), "r"(a[2]), "r"(a[3]), "r"(b[0]), "r"(b[1]));
}

// bf16 m16n8k16 mma, f32 accumulate
__device__ __forceinline__ void mma_bf16(float c[4], const uint32_t a[4], const uint32_t b[2])
{
    asm volatile(
        "mma.sync.aligned.m16n8k16.row.col.f32.bf16.bf16.f32 "
        "{%0,%1,%2,%3}, {%4,%5,%6,%7}, {%8,%9}, {%0,%1,%2,%3};\n"
        : "+f"(c[0]), "+f"(c[1]), "+f"(c[2]), "+f"(c[3])
        : "r"(a[0]), "r"(a[1]), "r"(a[2]), "r"(a[3]), "r"(b[0]), "r"(b[1]));
}

// pack two floats -> bf16x2 (lo = first k element)
__device__ __forceinline__ uint32_t packbf(float lo, float hi)
{
    uint32_t r;
    asm("cvt.rn.bf16x2.f32 %0, %1, %2;" : "=r"(r) : "f"(hi), "f"(lo));
    return r;
}

constexpr int AST = 132;   // A/T smem stride (u32)
constexpr int BST = 20;    // B-chunk smem stride

// one 16-k-slab of mma: A-src (stride AST), B-chunk (stride BST)
__device__ __forceinline__ void mma_slab16(const uint32_t* S, const uint32_t* Bb,
                                           float acc[4][4][4],
                                           int wm, int wn, int g, int tig, int kt)
{
#pragma unroll
    for (int k8s = 0; k8s < 2; ++k8s) {
        const int kk = kt * 16 + k8s * 8;
        uint32_t af[4][4];
#pragma unroll
        for (int mf = 0; mf < 4; ++mf) {
            const uint32_t* pa = S + (wm * 64 + mf * 16 + g) * AST + kk + tig;
            af[mf][0] = pa[0];
            af[mf][1] = pa[8 * AST];
            af[mf][2] = pa[4];
            af[mf][3] = pa[8 * AST + 4];
        }
        uint32_t bf[4][2];
#pragma unroll
        for (int nf = 0; nf < 4; ++nf) {
            const uint32_t* pb = Bb + (wn * 32 + nf * 8 + g) * BST + k8s * 8 + tig;
            bf[nf][0] = pb[0];
            bf[nf][1] = pb[4];
        }
#pragma unroll
        for (int mf = 0; mf < 4; ++mf)
#pragma unroll
            for (int nf = 0; nf < 4; ++nf)
                mma_tf32(acc[mf][nf], af[mf], bf[nf]);
    }
}

// epilogue shared by gemm_ar / mlp_fused
template<bool RELU, bool RESID, bool STATS>
__device__ __forceinline__ void gemm_epilogue(
    float acc[4][4][4], const float* bias, const float* resid,
    float* C, int ldc, int m0, int n0,
    int wm, int wn, int g, int tig, int tid,
    float* stats, float* sst /* 256-float smem scratch */)
{
    float cs[8], cq[8];
    if (STATS) {
#pragma unroll
        for (int j = 0; j < 8; ++j) { cs[j] = 0.f; cq[j] = 0.f; }
    }
#pragma unroll
    for (int mf = 0; mf < 4; ++mf) {
#pragma unroll
        for (int nf = 0; nf < 4; ++nf) {
            int row = m0 + wm * 64 + mf * 16 + g;
            int col = n0 + wn * 32 + nf * 8 + 2 * tig;
            float b0 = bias[col], b1 = bias[col + 1];
            float o00 = acc[mf][nf][0] + b0, o01 = acc[mf][nf][1] + b1;
            float o10 = acc[mf][nf][2] + b0, o11 = acc[mf][nf][3] + b1;
            if (RELU) {
                o00 = fmaxf(o00, 0.f); o01 = fmaxf(o01, 0.f);
                o10 = fmaxf(o10, 0.f); o11 = fmaxf(o11, 0.f);
            }
            if (RESID) {
                float2 r0 = *(const float2*)(resid + (size_t)row * ldc + col);
                float2 r1 = *(const float2*)(resid + (size_t)(row + 8) * ldc + col);
                o00 += r0.x; o01 += r0.y;
                o10 += r1.x; o11 += r1.y;
            }
            if (STATS) {
                cs[nf*2]   += o00 + o10;
                cs[nf*2+1] += o01 + o11;
                cq[nf*2]   += o00*o00 + o10*o10;
                cq[nf*2+1] += o01*o01 + o11*o11;
            }
            *(float2*)(C + (size_t)row * ldc + col)       = make_float2(o00, o01);
            *(float2*)(C + (size_t)(row + 8) * ldc + col) = make_float2(o10, o11);
        }
    }
    if (STATS) {
        __syncthreads();
        sst[tid] = 0.f;
        __syncthreads();
#pragma unroll
        for (int j = 0; j < 8; ++j) {
            int col = wn * 32 + (j >> 1) * 8 + 2 * tig + (j & 1);
            atomicAdd(&sst[col],       cs[j]);
            atomicAdd(&sst[128 + col], cq[j]);
        }
        __syncthreads();
        atomicAdd(&stats[tid], sst[tid]);
    }
}

// =====================================================================
// A-resident GEMM (K=128): C = A[128rows,128] @ B^T + bias (+resid)(+stats)
// =====================================================================
constexpr int GEMM_AR_SMEM = (128 * AST + 128 * BST) * 4;

template<bool RESID, bool STATS>
__global__ void __launch_bounds__(256, 2)
gemm_ar(const float* __restrict__ A,
        const float* __restrict__ B,
        const float* __restrict__ bias,
        const float* __restrict__ resid,
        float* __restrict__ C, int ldc,
        float* __restrict__ stats)
{
    extern __shared__ uint32_t sm[];
    uint32_t* Abuf = sm;               // [128][AST]
    uint32_t* Bbuf = sm + 128 * AST;   // [128][BST]

    const int tid = threadIdx.x;
    const int lane = tid & 31, warp = tid >> 5;
    const int wm = warp >> 2, wn = warp & 3;
    const int g = lane >> 2, tig = lane & 3;
    const int m0 = blockIdx.x * 128;
    const int n0 = blockIdx.y * 128;

#pragma unroll
    for (int it = 0; it < 16; ++it) {
        int idx = tid + it * 256;
        int r = idx >> 5, c4 = (idx & 31) * 4;
        float4 v = *(const float4*)(A + (size_t)(m0 + r) * 128 + c4);
        uint32_t* d = Abuf + r * AST + c4;
        d[0] = to_tf32(v.x); d[1] = to_tf32(v.y);
        d[2] = to_tf32(v.z); d[3] = to_tf32(v.w);
    }

    float acc[4][4][4];
#pragma unroll
    for (int i = 0; i < 4; ++i)
#pragma unroll
        for (int j = 0; j < 4; ++j)
#pragma unroll
            for (int r = 0; r < 4; ++r) acc[i][j][r] = 0.f;

    float4 pre0, pre1;
    {
        int i0 = tid, i1 = tid + 256;
        pre0 = *(const float4*)(B + (size_t)(n0 + (i0 >> 2)) * 128 + (i0 & 3) * 4);
        pre1 = *(const float4*)(B + (size_t)(n0 + (i1 >> 2)) * 128 + (i1 & 3) * 4);
    }

    for (int kt = 0; kt < 8; ++kt) {
        __syncthreads();
        {
            int i0 = tid, i1 = tid + 256;
            uint32_t* d0 = Bbuf + (i0 >> 2) * BST + (i0 & 3) * 4;
            d0[0] = to_tf32(pre0.x); d0[1] = to_tf32(pre0.y);
            d0[2] = to_tf32(pre0.z); d0[3] = to_tf32(pre0.w);
            uint32_t* d1 = Bbuf + (i1 >> 2) * BST + (i1 & 3) * 4;
            d1[0] = to_tf32(pre1.x); d1[1] = to_tf32(pre1.y);
            d1[2] = to_tf32(pre1.z); d1[3] = to_tf32(pre1.w);
        }
        if (kt < 7) {
            int i0 = tid, i1 = tid + 256;
            pre0 = *(const float4*)(B + (size_t)(n0 + (i0 >> 2)) * 128 + (kt + 1) * 16 + (i0 & 3) * 4);
            pre1 = *(const float4*)(B + (size_t)(n0 + (i1 >> 2)) * 128 + (kt + 1) * 16 + (i1 & 3) * 4);
        }
        __syncthreads();
        mma_slab16(Abuf, Bbuf, acc, wm, wn, g, tig, kt);
    }

    gemm_epilogue<false, RESID, STATS>(acc, bias, resid, C, ldc, m0, n0,
                                       wm, wn, g, tig, tid, stats, (float*)Bbuf);
}

// =====================================================================
// Fused MLP: C = relu(A @ W1 + b1) @ W2 + b2 (+resid)(+stats)
// =====================================================================
constexpr int MLP_SMEM = (2 * 128 * AST + 128 * BST) * 4;

template<int NC, bool STATS>
__global__ void __launch_bounds__(256, 1)
mlp_fused(const float* __restrict__ A,
          const float* __restrict__ W1, const float* __restrict__ b1,
          const float* __restrict__ W2, const float* __restrict__ b2,
          const float* __restrict__ resid,
          float* __restrict__ C,
          float* __restrict__ stats)
{
    extern __shared__ uint32_t sm[];
    uint32_t* Abuf = sm;                   // [128][AST]
    uint32_t* Tbuf = sm + 128 * AST;       // [128][AST]
    uint32_t* Bbuf = sm + 2 * 128 * AST;   // [128][BST]

    const int tid = threadIdx.x;
    const int lane = tid & 31, warp = tid >> 5;
    const int wm = warp >> 2, wn = warp & 3;
    const int g = lane >> 2, tig = lane & 3;
    const int m0 = blockIdx.x * 128;
    const int ldw1 = NC * 128;

#pragma unroll
    for (int it = 0; it < 16; ++it) {
        int idx = tid + it * 256;
        int r = idx >> 5, c4 = (idx & 31) * 4;
        float4 v = *(const float4*)(A + (size_t)(m0 + r) * 128 + c4);
        uint32_t* d = Abuf + r * AST + c4;
        d[0] = to_tf32(v.x); d[1] = to_tf32(v.y);
        d[2] = to_tf32(v.z); d[3] = to_tf32(v.w);
    }

    float co[4][4][4];
#pragma unroll
    for (int i = 0; i < 4; ++i)
#pragma unroll
        for (int j = 0; j < 4; ++j)
#pragma unroll
            for (int r = 0; r < 4; ++r) co[i][j][r] = 0.f;

    const int kk = tid >> 7;        // 0..1
    const int nn2 = tid & 127;      // n col

#pragma unroll
    for (int nc = 0; nc < NC; ++nc) {
        float c1[4][4][4];
#pragma unroll
        for (int i = 0; i < 4; ++i)
#pragma unroll
            for (int j = 0; j < 4; ++j)
#pragma unroll
                for (int r = 0; r < 4; ++r) c1[i][j][r] = 0.f;

        float pre[8];
#pragma unroll
        for (int j = 0; j < 8; ++j)
            pre[j] = W1[(size_t)(j * 2 + kk) * ldw1 + nc * 128 + nn2];

        for (int kt = 0; kt < 8; ++kt) {
            __syncthreads();
#pragma unroll
            for (int j = 0; j < 8; ++j)
                Bbuf[nn2 * BST + j * 2 + kk] = to_tf32(pre[j]);
            if (kt < 7) {
#pragma unroll
                for (int j = 0; j < 8; ++j)
                    pre[j] = W1[(size_t)((kt + 1) * 16 + j * 2 + kk) * ldw1 + nc * 128 + nn2];
            }
            __syncthreads();
            mma_slab16(Abuf, Bbuf, c1, wm, wn, g, tig, kt);
        }

#pragma unroll
        for (int mf = 0; mf < 4; ++mf) {
#pragma unroll
            for (int nf = 0; nf < 4; ++nf) {
                int row = wm * 64 + mf * 16 + g;
                int col = wn * 32 + nf * 8 + 2 * tig;
                float bb0 = b1[nc * 128 + col], bb1 = b1[nc * 128 + col + 1];
                Tbuf[row * AST + col]           = to_tf32(fmaxf(c1[mf][nf][0] + bb0, 0.f));
                Tbuf[row * AST + col + 1]       = to_tf32(fmaxf(c1[mf][nf][1] + bb1, 0.f));
                Tbuf[(row + 8) * AST + col]     = to_tf32(fmaxf(c1[mf][nf][2] + bb0, 0.f));
                Tbuf[(row + 8) * AST + col + 1] = to_tf32(fmaxf(c1[mf][nf][3] + bb1, 0.f));
            }
        }

#pragma unroll
        for (int j = 0; j < 8; ++j)
            pre[j] = W2[(size_t)(nc * 128 + j * 2 + kk) * 128 + nn2];

        for (int kt = 0; kt < 8; ++kt) {
            __syncthreads();
#pragma unroll
            for (int j = 0; j < 8; ++j)
                Bbuf[nn2 * BST + j * 2 + kk] = to_tf32(pre[j]);
            if (kt < 7) {
#pragma unroll
                for (int j = 0; j < 8; ++j)
                    pre[j] = W2[(size_t)(nc * 128 + (kt + 1) * 16 + j * 2 + kk) * 128 + nn2];
            }
            __syncthreads();
            mma_slab16(Tbuf, Bbuf, co, wm, wn, g, tig, kt);
        }
    }

    gemm_epilogue<false, true, STATS>(co, b2, resid, C, 128, m0, 0,
                                      wm, wn, g, tig, tid, stats, (float*)Bbuf);
}

// =====================================================================
// Flash-style BF16 attention, v3: S c-frags ARE PV a-frags (no transpose).
// Block = (graph, head, half), warp = 32 q rows.
// K packed bf16x2 along d (Ksp[512][12]), V packed along kv (Vsp[256][24]).
// =====================================================================
constexpr int KP_ST = 12;   // bank-conflict-free: (12g+tig) mod 32 all distinct
constexpr int VP_ST = 24;   // (24*tig+g) mod 32 all distinct
constexpr int ATTN_SMEM = (512 * KP_ST + 256 * VP_ST) * 4;   // 48KB

__global__ void __launch_bounds__(256, 2)
attn_mma(const float* __restrict__ qkv, float* __restrict__ ao)
{
    extern __shared__ uint32_t sm[];
    uint32_t* Ksp = sm;                   // [512 kv][12]  bf16x2 pairs along d
    uint32_t* Vsp = sm + 512 * KP_ST;     // [256 kvpair][24] bf16x2 pairs along kv

    const int tid  = threadIdx.x;
    const int lane = tid & 31;
    const int warp = tid >> 5;
    const int g    = lane >> 2;   // 0..7
    const int tig  = lane & 3;    // 0..3
    const int b    = blockIdx.x;
    const int gi = b >> 4, h = (b >> 1) & 7, half = b & 1;
    const float* base = qkv + (size_t)gi * SEQ * 384;
    const int m0 = half * 256 + warp * 32;

    // ---- stage K (pack along d) and V (pack along kv) ----
    for (int idx = tid; idx < 2048; idx += 256) {
        int r = idx >> 2, c4 = (idx & 3) * 4;
        float4 kv = *(const float4*)(base + (size_t)r * 384 + 128 + h * 16 + c4);
        Ksp[r * KP_ST + (c4 >> 1)]     = packbf(kv.x, kv.y);
        Ksp[r * KP_ST + (c4 >> 1) + 1] = packbf(kv.z, kv.w);
        if (idx < 1024) {
            int pr = r, dg = c4;   // pr 0..255
            float4 v0 = *(const float4*)(base + (size_t)(2 * pr)     * 384 + 256 + h * 16 + dg);
            float4 v1 = *(const float4*)(base + (size_t)(2 * pr + 1) * 384 + 256 + h * 16 + dg);
            uint32_t* vd = Vsp + pr * VP_ST + dg;
            vd[0] = packbf(v0.x, v1.x);
            vd[1] = packbf(v0.y, v1.y);
            vd[2] = packbf(v0.z, v1.z);
            vd[3] = packbf(v0.w, v1.w);
        }
    }

    // ---- Q a-frags (bf16, scale 0.25 folded) ----
    uint32_t qa[2][4];
#pragma unroll
    for (int mt = 0; mt < 2; ++mt) {
        const float* qp = base + (size_t)(m0 + mt * 16 + g) * 384 + h * 16;
        float2 a0 = *(const float2*)(qp + 2 * tig);
        float2 a1 = *(const float2*)(qp + 8 * 384 + 2 * tig);
        float2 a2 = *(const float2*)(qp + 2 * tig + 8);
        float2 a3 = *(const float2*)(qp + 8 * 384 + 2 * tig + 8);
        qa[mt][0] = packbf(a0.x * 0.25f, a0.y * 0.25f);
        qa[mt][1] = packbf(a1.x * 0.25f, a1.y * 0.25f);
        qa[mt][2] = packbf(a2.x * 0.25f, a2.y * 0.25f);
        qa[mt][3] = packbf(a3.x * 0.25f, a3.y * 0.25f);
    }
    __syncthreads();

    float o[2][2][4];
    float lrow[2][2];
#pragma unroll
    for (int mt = 0; mt < 2; ++mt) {
        lrow[mt][0] = 0.f; lrow[mt][1] = 0.f;
#pragma unroll
        for (int nt = 0; nt < 2; ++nt)
#pragma unroll
            for (int r = 0; r < 4; ++r) o[mt][nt][r] = 0.f;
    }

    for (int j = 0; j < 16; ++j) {      // kv chunk of 32
        const int n0 = j * 32;
        uint32_t ps[2][2][4];           // [mt][k16chunk][a-reg] — P a-frags

#pragma unroll
        for (int nt = 0; nt < 4; ++nt) {
            // K b-frag for kv cols n0+nt*8 .. +7
            uint32_t bk[2];
            {
                const uint32_t* kp = Ksp + (n0 + nt * 8 + g) * KP_ST + tig;
                bk[0] = kp[0];
                bk[1] = kp[4];
            }
#pragma unroll
            for (int mt = 0; mt < 2; ++mt) {
                float c[4] = {0.f, 0.f, 0.f, 0.f};
                mma_bf16(c, qa[mt], bk);
                float p0 = __expf(c[0]);
                float p1 = __expf(c[1]);
                float p2 = __expf(c[2]);
                float p3 = __expf(c[3]);
                lrow[mt][0] += p0 + p1;
                lrow[mt][1] += p2 + p3;
                // S c-frag == P a-frag: pack pairs directly
                ps[mt][nt >> 1][(nt & 1) * 2 + 0] = packbf(p0, p1);  // row g
                ps[mt][nt >> 1][(nt & 1) * 2 + 1] = packbf(p2, p3);  // row g+8
            }
        }

        // O += P @ V  (two k16 chunks)
#pragma unroll
        for (int c = 0; c < 2; ++c) {
            const int prb = (n0 >> 1) + c * 8;
#pragma unroll
            for (int nt = 0; nt < 2; ++nt) {
                uint32_t bv[2];
                const uint32_t* vp = Vsp + (prb + tig) * VP_ST + nt * 8 + g;
                bv[0] = vp[0];
                bv[1] = vp[4 * VP_ST];
#pragma unroll
                for (int mt = 0; mt < 2; ++mt)
                    mma_bf16(o[mt][nt], ps[mt][c], bv);
            }
        }
    }

    // ---- normalize + write ----
#pragma unroll
    for (int mt = 0; mt < 2; ++mt) {
        float l0 = lrow[mt][0], l1 = lrow[mt][1];
        l0 += __shfl_xor_sync(0xffffffffu, l0, 1);
        l0 += __shfl_xor_sync(0xffffffffu, l0, 2);
        l1 += __shfl_xor_sync(0xffffffffu, l1, 1);
        l1 += __shfl_xor_sync(0xffffffffu, l1, 2);
        float i0 = 1.f / l0, i1 = 1.f / l1;
        int grow = gi * SEQ + m0 + mt * 16 + g;
#pragma unroll
        for (int nt = 0; nt < 2; ++nt) {
            int col = h * 16 + nt * 8 + 2 * tig;
            *(float2*)(ao + (size_t)grow * DD + col) =
                make_float2(o[mt][nt][0] * i0, o[mt][nt][1] * i0);
            *(float2*)(ao + (size_t)(grow + 8) * DD + col) =
                make_float2(o[mt][nt][2] * i1, o[mt][nt][3] * i1);
        }
    }
}

// =====================================================================
// BatchNorm applies
// =====================================================================
__device__ __forceinline__ void bn_coef(const float* stats, const float* gamma,
                                        const float* beta, int col,
                                        float& sc, float& sh)
{
    float mean = stats[col] * (1.f / (float)NN);
    float var  = stats[128 + col] * (1.f / (float)NN) - mean * mean;
    sc = gamma[col] * rsqrtf(var + 1e-5f);
    sh = beta[col] - mean * sc;
}

__global__ void __launch_bounds__(256)
bn_apply_one(const float* __restrict__ X, const float* __restrict__ stats,
             const float* __restrict__ gamma, const float* __restrict__ beta,
             float* __restrict__ out)
{
    int col = threadIdx.x & 127;
    int half = threadIdx.x >> 7;
    float sc, sh;
    bn_coef(stats, gamma, beta, col, sc, sh);
    int row0 = blockIdx.x * 128 + half * 64;
    size_t off = (size_t)row0 * DD + col;
#pragma unroll 4
    for (int r = 0; r < 64; ++r)
        out[off + r * DD] = X[off + r * DD] * sc + sh;
}

__global__ void __launch_bounds__(256)
bn_apply_dual(const float* __restrict__ ha, const float* __restrict__ statsA,
              const float* __restrict__ ga, const float* __restrict__ ba,
              const float* __restrict__ hl, const float* __restrict__ statsL,
              const float* __restrict__ gl, const float* __restrict__ bl,
              float* __restrict__ out)
{
    int col = threadIdx.x & 127;
    int half = threadIdx.x >> 7;
    float scA, shA, scL, shL;
    bn_coef(statsA, ga, ba, col, scA, shA);
    bn_coef(statsL, gl, bl, col, scL, shL);
    int row0 = blockIdx.x * 128 + half * 64;
    size_t off = (size_t)row0 * DD + col;
#pragma unroll 4
    for (int r = 0; r < 64; ++r)
        out[off + r * DD] = ha[off + r * DD] * scA + shA
                          + hl[off + r * DD] * scL + shL;
}

// =====================================================================
// Host launcher
// =====================================================================
extern "C" void kernel_launch(void* const* d_in, const int* in_sizes, int n_in,
                              void* d_out, int out_size)
{
    const float* x          = (const float*)d_in[0];
    const int*   edge_index = (const int*)  d_in[1];
    const float* edge_attr  = (const float*)d_in[2];
    const float* gin_w1     = (const float*)d_in[3];
    const float* gin_b1     = (const float*)d_in[4];
    const float* gin_w2     = (const float*)d_in[5];
    const float* gin_b2     = (const float*)d_in[6];
    const float* bn1l_g     = (const float*)d_in[7];
    const float* bn1l_b     = (const float*)d_in[8];
    const float* in_proj_w  = (const float*)d_in[9];
    const float* in_proj_b  = (const float*)d_in[10];
    const float* out_proj_w = (const float*)d_in[11];
    const float* out_proj_b = (const float*)d_in[12];
    const float* bn1a_g     = (const float*)d_in[13];
    const float* bn1a_b     = (const float*)d_in[14];
    const float* ff_w1      = (const float*)d_in[15];
    const float* ff_b1      = (const float*)d_in[16];
    const float* ff_w2      = (const float*)d_in[17];
    const float* ff_b2      = (const float*)d_in[18];
    const float* bn2_g      = (const float*)d_in[19];
    const float* bn2_b      = (const float*)d_in[20];
    float* out = (float*)d_out;

    cudaFuncSetAttribute(attn_mma, cudaFuncAttributeMaxDynamicSharedMemorySize, ATTN_SMEM);
    cudaFuncSetAttribute(gemm_ar<false, false>, cudaFuncAttributeMaxDynamicSharedMemorySize, GEMM_AR_SMEM);
    cudaFuncSetAttribute(gemm_ar<true,  true >, cudaFuncAttributeMaxDynamicSharedMemorySize, GEMM_AR_SMEM);
    cudaFuncSetAttribute(mlp_fused<1, true>, cudaFuncAttributeMaxDynamicSharedMemorySize, MLP_SMEM);
    cudaFuncSetAttribute(mlp_fused<2, true>, cudaFuncAttributeMaxDynamicSharedMemorySize, MLP_SMEM);

    float *z, *hl, *qkvb, *ao, *ha, *h, *h2, *stats;
    int *deg, *off, *pos, *eid;
    cudaGetSymbolAddress((void**)&z,    g_z);
    cudaGetSymbolAddress((void**)&hl,   g_hl);
    cudaGetSymbolAddress((void**)&qkvb, g_qkv);
    cudaGetSymbolAddress((void**)&ao,   g_ao);
    cudaGetSymbolAddress((void**)&ha,   g_ha);
    cudaGetSymbolAddress((void**)&h,    g_h);
    cudaGetSymbolAddress((void**)&h2,   g_h2);
    cudaGetSymbolAddress((void**)&stats, g_stats);
    cudaGetSymbolAddress((void**)&deg,  g_deg);
    cudaGetSymbolAddress((void**)&off,  g_off);
    cudaGetSymbolAddress((void**)&pos,  g_pos);
    cudaGetSymbolAddress((void**)&eid,  g_eid);

    const int* src = edge_index;
    const int* dst = edge_index + EE;
    const dim3 blk(256);
    const int GB = NN / 128;

    float* stats_hl = stats;
    float* stats_ha = stats + 256;
    float* stats_h2 = stats + 512;

    // launch order keeps attn_mma at profile index 3
    zero_misc<<<64, blk>>>(deg, stats);                                            // 0
    gemm_ar<false, false><<<dim3(GB, 3), blk, GEMM_AR_SMEM>>>(x, in_proj_w, in_proj_b,
                                                              nullptr, qkvb, 384, nullptr);  // 1: QKV
    count_kernel<<<EE / 256, blk>>>(dst, deg);                                     // 2
    attn_mma<<<NGR * NH * 2, blk, ATTN_SMEM>>>(qkvb, ao);                          // 3  <- profiled
    scan_kernel<<<1, 1024>>>(deg, off, pos);                                       // 4
    scatter_kernel<<<EE / 256, blk>>>(dst, pos, eid);                              // 5
    aggr_kernel<<<NN / 8, blk>>>(x, src, edge_attr, off, eid, z);                  // 6
    mlp_fused<1, true><<<GB, blk, MLP_SMEM>>>(z, gin_w1, gin_b1, gin_w2, gin_b2,
                                              x, hl, stats_hl);                    // 7: GINE MLP
    gemm_ar<true, true><<<dim3(GB, 1), blk, GEMM_AR_SMEM>>>(ao, out_proj_w, out_proj_b,
                                                            x, ha, 128, stats_ha); // 8: out_proj
    bn_apply_dual<<<128, blk>>>(ha, stats_ha, bn1a_g, bn1a_b,
                                hl, stats_hl, bn1l_g, bn1l_b, h);                  // 9
    mlp_fused<2, true><<<GB, blk, MLP_SMEM>>>(h, ff_w1, ff_b1, ff_w2, ff_b2,
                                              h, h2, stats_h2);                    // 10: FFN
    bn_apply_one<<<128, blk>>>(h2, stats_h2, bn2_g, bn2_b, out);                   // 11
}

// round 10
// speedup vs baseline: 1.2384x; 1.0796x over previous
#include <cuda_runtime.h>
#include <cuda_bf16.h>
#include <math.h>
#include <stdint.h>

// Problem constants
constexpr int NN  = 16384;   // nodes
constexpr int DD  = 128;     // dim
constexpr int EE  = 262144;  // edges
constexpr int SEQ = 512;     // nodes per graph
constexpr int NGR = 32;      // graphs
constexpr int NH  = 8;       // heads (dh = 16)

// ---------------- scratch ----------------
__device__ float g_z   [NN * DD];
__device__ float g_hl  [NN * DD];
__device__ float g_qkv [NN * 3 * DD];
__device__ float g_ao  [NN * DD];
__device__ float g_ha  [NN * DD];
__device__ float g_h   [NN * DD];
__device__ float g_h2  [NN * DD];
__device__ float g_stats[768];   // [0:256) hl, [256:512) ha, [512:768) h2
__device__ int   g_deg [NN];
__device__ int   g_off [NN + 1];
__device__ int   g_pos [NN];
__device__ int   g_eid [EE];

// =====================================================================
__global__ void zero_misc(int* deg, float* stats)
{
    int i = blockIdx.x * 256 + threadIdx.x;
    deg[i] = 0;
    if (i < 768) stats[i] = 0.f;
}

// =====================================================================
// CSR build by dst:  count -> scan -> scatter
// =====================================================================
__global__ void count_kernel(const int* __restrict__ dst, int* __restrict__ deg)
{
    int e = blockIdx.x * 256 + threadIdx.x;
    atomicAdd(&deg[dst[e]], 1);
}

__global__ void __launch_bounds__(1024)
scan_kernel(const int* __restrict__ deg, int* __restrict__ off, int* __restrict__ pos)
{
    __shared__ int buf[2][1024];
    int t = threadIdx.x;
    int base = t * 16;
    int loc[16];
    int sum = 0;
#pragma unroll
    for (int i = 0; i < 16; ++i) { loc[i] = sum; sum += deg[base + i]; }
    buf[0][t] = sum;
    __syncthreads();
    int sel = 0;
    for (int d = 1; d < 1024; d <<= 1) {
        int v = buf[sel][t] + (t >= d ? buf[sel][t - d] : 0);
        buf[sel ^ 1][t] = v;
        sel ^= 1;
        __syncthreads();
    }
    int excl = buf[sel][t] - sum;
#pragma unroll
    for (int i = 0; i < 16; ++i) {
        int o = excl + loc[i];
        off[base + i] = o;
        pos[base + i] = o;
    }
    if (t == 1023) off[NN] = excl + sum;
}

__global__ void scatter_kernel(const int* __restrict__ dst, int* __restrict__ pos,
                               int* __restrict__ eid)
{
    int e = blockIdx.x * 256 + threadIdx.x;
    int p = atomicAdd(&pos[dst[e]], 1);
    eid[p] = e;
}

// =====================================================================
// Gather aggregation: z = x + sum_{e -> node} relu(x[src[e]] + ea[e])
// =====================================================================
__global__ void __launch_bounds__(256)
aggr_kernel(const float* __restrict__ x, const int* __restrict__ src,
            const float* __restrict__ ea, const int* __restrict__ off,
            const int* __restrict__ eid, float* __restrict__ z)
{
    int node = blockIdx.x * 8 + (threadIdx.x >> 5);
    int lane = threadIdx.x & 31;
    int beg = off[node], end = off[node + 1];
    const float4* x4  = (const float4*)x;
    const float4* ea4 = (const float4*)ea;
    float4 acc = make_float4(0.f, 0.f, 0.f, 0.f);
#pragma unroll 2
    for (int i = beg; i < end; ++i) {
        int e = __ldg(eid + i);
        int s = __ldg(src + e);
        float4 a = x4[(size_t)s * 32 + lane];
        float4 b = ea4[(size_t)e * 32 + lane];
        acc.x += fmaxf(a.x + b.x, 0.f);
        acc.y += fmaxf(a.y + b.y, 0.f);
        acc.z += fmaxf(a.z + b.z, 0.f);
        acc.w += fmaxf(a.w + b.w, 0.f);
    }
    float4 xv = x4[(size_t)node * 32 + lane];
    ((float4*)z)[(size_t)node * 32 + lane] =
        make_float4(xv.x + acc.x, xv.y + acc.y, xv.z + acc.z, xv.w + acc.w);
}

// =====================================================================
// mma helpers
// =====================================================================
__device__ __forceinline__ uint32_t to_tf32(float f)
{
    uint32_t u;
    asm("cvt.rna.tf32.f32 %0, %1;" : "=r"(u) : "f"(f));
    return u;
}

__device__ __forceinline__ void mma_tf32(float c[4], const uint32_t a[4], const uint32_t b[2])
{
    asm volatile(
        "mma.sync.aligned.m16n8k8.row.col.f32.tf32.tf32.f32 "
        "{%0,%1,%2,%3}, {%4,%5,%6,%7}, {%8,%9}, {%0,%1,%2,%3};\n"
        : "+f"(c[0]), "+f"(c[1]), "+f"(c[2]), "+f"(c[3])
        : "r"(a[0]), "r"(a[1]), "r"(a[2]), "r"(a[3]), "r"(b[0]), "r"(b[1]));
}

// bf16 m16n8k16 mma, f32 accumulate
__device__ __forceinline__ void mma_bf16(float c[4], const uint32_t a[4], const uint32_t b[2])
{
    asm volatile(
        "mma.sync.aligned.m16n8k16.row.col.f32.bf16.bf16.f32 "
        "{%0,%1,%2,%3}, {%4,%5,%6,%7}, {%8,%9}, {%0,%1,%2,%3};\n"
        : "+f"(c[0]), "+f"(c[1]), "+f"(c[2]), "+f"(c[3])
        : "r"(a[0]), "r"(a[1]), "r"(a[2]), "r"(a[3]), "r"(b[0]), "r"(b[1]));
}

// pack two floats -> bf16x2 (lo = first k element)
__device__ __forceinline__ uint32_t packbf(float lo, float hi)
{
    uint32_t r;
    asm("cvt.rn.bf16x2.f32 %0, %1, %2;" : "=r"(r) : "f"(hi), "f"(lo));
    return r;
}

__device__ __forceinline__ float fex2(float x)
{
    float y;
    asm("ex2.approx.f32 %0, %1;" : "=f"(y) : "f"(x));
    return y;
}

constexpr int AST = 132;   // A/T smem stride (u32)
constexpr int BST = 20;    // B-chunk smem stride

// one 16-k-slab of mma: A-src (stride AST), B-chunk (stride BST)
__device__ __forceinline__ void mma_slab16(const uint32_t* S, const uint32_t* Bb,
                                           float acc[4][4][4],
                                           int wm, int wn, int g, int tig, int kt)
{
#pragma unroll
    for (int k8s = 0; k8s < 2; ++k8s) {
        const int kk = kt * 16 + k8s * 8;
        uint32_t af[4][4];
#pragma unroll
        for (int mf = 0; mf < 4; ++mf) {
            const uint32_t* pa = S + (wm * 64 + mf * 16 + g) * AST + kk + tig;
            af[mf][0] = pa[0];
            af[mf][1] = pa[8 * AST];
            af[mf][2] = pa[4];
            af[mf][3] = pa[8 * AST + 4];
        }
        uint32_t bf[4][2];
#pragma unroll
        for (int nf = 0; nf < 4; ++nf) {
            const uint32_t* pb = Bb + (wn * 32 + nf * 8 + g) * BST + k8s * 8 + tig;
            bf[nf][0] = pb[0];
            bf[nf][1] = pb[4];
        }
#pragma unroll
        for (int mf = 0; mf < 4; ++mf)
#pragma unroll
            for (int nf = 0; nf < 4; ++nf)
                mma_tf32(acc[mf][nf], af[mf], bf[nf]);
    }
}

// epilogue shared by gemm_ar / mlp_fused
template<bool RELU, bool RESID, bool STATS>
__device__ __forceinline__ void gemm_epilogue(
    float acc[4][4][4], const float* bias, const float* resid,
    float* C, int ldc, int m0, int n0,
    int wm, int wn, int g, int tig, int tid,
    float* stats, float* sst /* 256-float smem scratch */)
{
    float cs[8], cq[8];
    if (STATS) {
#pragma unroll
        for (int j = 0; j < 8; ++j) { cs[j] = 0.f; cq[j] = 0.f; }
    }
#pragma unroll
    for (int mf = 0; mf < 4; ++mf) {
#pragma unroll
        for (int nf = 0; nf < 4; ++nf) {
            int row = m0 + wm * 64 + mf * 16 + g;
            int col = n0 + wn * 32 + nf * 8 + 2 * tig;
            float b0 = bias[col], b1 = bias[col + 1];
            float o00 = acc[mf][nf][0] + b0, o01 = acc[mf][nf][1] + b1;
            float o10 = acc[mf][nf][2] + b0, o11 = acc[mf][nf][3] + b1;
            if (RELU) {
                o00 = fmaxf(o00, 0.f); o01 = fmaxf(o01, 0.f);
                o10 = fmaxf(o10, 0.f); o11 = fmaxf(o11, 0.f);
            }
            if (RESID) {
                float2 r0 = *(const float2*)(resid + (size_t)row * ldc + col);
                float2 r1 = *(const float2*)(resid + (size_t)(row + 8) * ldc + col);
                o00 += r0.x; o01 += r0.y;
                o10 += r1.x; o11 += r1.y;
            }
            if (STATS) {
                cs[nf*2]   += o00 + o10;
                cs[nf*2+1] += o01 + o11;
                cq[nf*2]   += o00*o00 + o10*o10;
                cq[nf*2+1] += o01*o01 + o11*o11;
            }
            *(float2*)(C + (size_t)row * ldc + col)       = make_float2(o00, o01);
            *(float2*)(C + (size_t)(row + 8) * ldc + col) = make_float2(o10, o11);
        }
    }
    if (STATS) {
        __syncthreads();
        sst[tid] = 0.f;
        __syncthreads();
#pragma unroll
        for (int j = 0; j < 8; ++j) {
            int col = wn * 32 + (j >> 1) * 8 + 2 * tig + (j & 1);
            atomicAdd(&sst[col],       cs[j]);
            atomicAdd(&sst[128 + col], cq[j]);
        }
        __syncthreads();
        atomicAdd(&stats[tid], sst[tid]);
    }
}

// =====================================================================
// A-resident GEMM (K=128): C = A[128rows,128] @ B^T + bias (+resid)(+stats)
// Double-buffered B chunks: ONE sync per k-chunk.
// =====================================================================
constexpr int GEMM_AR_SMEM = (128 * AST + 2 * 128 * BST) * 4;

template<bool RESID, bool STATS>
__global__ void __launch_bounds__(256, 2)
gemm_ar(const float* __restrict__ A,
        const float* __restrict__ B,
        const float* __restrict__ bias,
        const float* __restrict__ resid,
        float* __restrict__ C, int ldc,
        float* __restrict__ stats)
{
    extern __shared__ uint32_t sm[];
    uint32_t* Abuf = sm;               // [128][AST]
    uint32_t* Bb0  = sm + 128 * AST;   // stage 0
    uint32_t* Bb1  = Bb0 + 128 * BST;  // stage 1

    const int tid = threadIdx.x;
    const int lane = tid & 31, warp = tid >> 5;
    const int wm = warp >> 2, wn = warp & 3;
    const int g = lane >> 2, tig = lane & 3;
    const int m0 = blockIdx.x * 128;
    const int n0 = blockIdx.y * 128;
    const int i0 = tid, i1 = tid + 256;
    const float* Bp0 = B + (size_t)(n0 + (i0 >> 2)) * 128 + (i0 & 3) * 4;
    const float* Bp1 = B + (size_t)(n0 + (i1 >> 2)) * 128 + (i1 & 3) * 4;
    const int o0 = (i0 >> 2) * BST + (i0 & 3) * 4;   // ELEMENT offsets (bugfix)
    const int o1 = (i1 >> 2) * BST + (i1 & 3) * 4;

#pragma unroll
    for (int it = 0; it < 16; ++it) {
        int idx = tid + it * 256;
        int r = idx >> 5, c4 = (idx & 31) * 4;
        float4 v = *(const float4*)(A + (size_t)(m0 + r) * 128 + c4);
        uint32_t* d = Abuf + r * AST + c4;
        d[0] = to_tf32(v.x); d[1] = to_tf32(v.y);
        d[2] = to_tf32(v.z); d[3] = to_tf32(v.w);
    }

    float acc[4][4][4];
#pragma unroll
    for (int i = 0; i < 4; ++i)
#pragma unroll
        for (int j = 0; j < 4; ++j)
#pragma unroll
            for (int r = 0; r < 4; ++r) acc[i][j][r] = 0.f;

    // chunk 0 -> stage 0, prefetch chunk 1
    float4 pre0 = *(const float4*)(Bp0);
    float4 pre1 = *(const float4*)(Bp1);
    {
        uint32_t* d0 = Bb0 + o0;
        d0[0] = to_tf32(pre0.x); d0[1] = to_tf32(pre0.y);
        d0[2] = to_tf32(pre0.z); d0[3] = to_tf32(pre0.w);
        uint32_t* d1 = Bb0 + o1;
        d1[0] = to_tf32(pre1.x); d1[1] = to_tf32(pre1.y);
        d1[2] = to_tf32(pre1.z); d1[3] = to_tf32(pre1.w);
    }
    pre0 = *(const float4*)(Bp0 + 16);
    pre1 = *(const float4*)(Bp1 + 16);
    __syncthreads();

    for (int kt = 0; kt < 8; ++kt) {
        if (kt < 7) {
            uint32_t* stg = (kt & 1) ? Bb0 : Bb1;   // stage (kt+1)&1
            uint32_t* d0 = stg + o0;
            d0[0] = to_tf32(pre0.x); d0[1] = to_tf32(pre0.y);
            d0[2] = to_tf32(pre0.z); d0[3] = to_tf32(pre0.w);
            uint32_t* d1 = stg + o1;
            d1[0] = to_tf32(pre1.x); d1[1] = to_tf32(pre1.y);
            d1[2] = to_tf32(pre1.z); d1[3] = to_tf32(pre1.w);
            if (kt < 6) {
                pre0 = *(const float4*)(Bp0 + (kt + 2) * 16);
                pre1 = *(const float4*)(Bp1 + (kt + 2) * 16);
            }
        }
        mma_slab16(Abuf, (kt & 1) ? Bb1 : Bb0, acc, wm, wn, g, tig, kt);
        if (kt < 7) __syncthreads();
    }

    gemm_epilogue<false, RESID, STATS>(acc, bias, resid, C, ldc, m0, n0,
                                       wm, wn, g, tig, tid, stats, (float*)Bb0);
}

// =====================================================================
// Fused MLP: C = relu(A @ W1 + b1) @ W2 + b2 (+resid)(+stats)
// Double-buffered B chunks, one sync per chunk.
// =====================================================================
constexpr int MLP_SMEM = (2 * 128 * AST + 2 * 128 * BST) * 4;

template<int NC, bool STATS>
__global__ void __launch_bounds__(256, 1)
mlp_fused(const float* __restrict__ A,
          const float* __restrict__ W1, const float* __restrict__ b1,
          const float* __restrict__ W2, const float* __restrict__ b2,
          const float* __restrict__ resid,
          float* __restrict__ C,
          float* __restrict__ stats)
{
    extern __shared__ uint32_t sm[];
    uint32_t* Abuf = sm;                   // [128][AST]
    uint32_t* Tbuf = sm + 128 * AST;       // [128][AST]
    uint32_t* Bb0  = sm + 2 * 128 * AST;   // stage 0
    uint32_t* Bb1  = Bb0 + 128 * BST;      // stage 1

    const int tid = threadIdx.x;
    const int lane = tid & 31, warp = tid >> 5;
    const int wm = warp >> 2, wn = warp & 3;
    const int g = lane >> 2, tig = lane & 3;
    const int m0 = blockIdx.x * 128;
    const int ldw1 = NC * 128;

    const int kk = tid >> 7;        // 0..1
    const int nn2 = tid & 127;      // n col
    const int ob = nn2 * BST + kk;  // ELEMENT store offset base

#pragma unroll
    for (int it = 0; it < 16; ++it) {
        int idx = tid + it * 256;
        int r = idx >> 5, c4 = (idx & 31) * 4;
        float4 v = *(const float4*)(A + (size_t)(m0 + r) * 128 + c4);
        uint32_t* d = Abuf + r * AST + c4;
        d[0] = to_tf32(v.x); d[1] = to_tf32(v.y);
        d[2] = to_tf32(v.z); d[3] = to_tf32(v.w);
    }

    float co[4][4][4];
#pragma unroll
    for (int i = 0; i < 4; ++i)
#pragma unroll
        for (int j = 0; j < 4; ++j)
#pragma unroll
            for (int r = 0; r < 4; ++r) co[i][j][r] = 0.f;

#pragma unroll
    for (int nc = 0; nc < NC; ++nc) {
        // ============ phase 1: c1 = A @ W1[:, nc*128..] ============
        float c1[4][4][4];
#pragma unroll
        for (int i = 0; i < 4; ++i)
#pragma unroll
            for (int j = 0; j < 4; ++j)
#pragma unroll
                for (int r = 0; r < 4; ++r) c1[i][j][r] = 0.f;

        const float* Wp = W1 + nc * 128 + nn2;
        float pre[8];
#pragma unroll
        for (int j = 0; j < 8; ++j)
            pre[j] = Wp[(size_t)(j * 2 + kk) * ldw1];
        if (nc) __syncthreads();  // protect Bb0 from previous phase-2 kt=6 reads
#pragma unroll
        for (int j = 0; j < 8; ++j)
            Bb0[ob + j * 2] = to_tf32(pre[j]);
#pragma unroll
        for (int j = 0; j < 8; ++j)
            pre[j] = Wp[(size_t)(16 + j * 2 + kk) * ldw1];
        __syncthreads();

        for (int kt = 0; kt < 8; ++kt) {
            if (kt < 7) {
                uint32_t* stg = (kt & 1) ? Bb0 : Bb1;
#pragma unroll
                for (int j = 0; j < 8; ++j)
                    stg[ob + j * 2] = to_tf32(pre[j]);
                if (kt < 6) {
#pragma unroll
                    for (int j = 0; j < 8; ++j)
                        pre[j] = Wp[(size_t)((kt + 2) * 16 + j * 2 + kk) * ldw1];
                }
            }
            mma_slab16(Abuf, (kt & 1) ? Bb1 : Bb0, c1, wm, wn, g, tig, kt);
            if (kt < 7) __syncthreads();
        }

        // write hidden tile: relu(c1 + b1chunk) -> Tbuf (tf32)
#pragma unroll
        for (int mf = 0; mf < 4; ++mf) {
#pragma unroll
            for (int nf = 0; nf < 4; ++nf) {
                int row = wm * 64 + mf * 16 + g;
                int col = wn * 32 + nf * 8 + 2 * tig;
                float bb0 = b1[nc * 128 + col], bb1 = b1[nc * 128 + col + 1];
                Tbuf[row * AST + col]           = to_tf32(fmaxf(c1[mf][nf][0] + bb0, 0.f));
                Tbuf[row * AST + col + 1]       = to_tf32(fmaxf(c1[mf][nf][1] + bb1, 0.f));
                Tbuf[(row + 8) * AST + col]     = to_tf32(fmaxf(c1[mf][nf][2] + bb0, 0.f));
                Tbuf[(row + 8) * AST + col + 1] = to_tf32(fmaxf(c1[mf][nf][3] + bb1, 0.f));
            }
        }

        // ============ phase 2: co += T @ W2[nc*128.., :] ============
        const float* W2p = W2 + (size_t)nc * 128 * 128 + nn2;
#pragma unroll
        for (int j = 0; j < 8; ++j)
            pre[j] = W2p[(size_t)(j * 2 + kk) * 128];
        __syncthreads();  // all warps past phase-1 kt=6 mma (Bb0 free)
#pragma unroll
        for (int j = 0; j < 8; ++j)
            Bb0[ob + j * 2] = to_tf32(pre[j]);
#pragma unroll
        for (int j = 0; j < 8; ++j)
            pre[j] = W2p[(size_t)(16 + j * 2 + kk) * 128];
        __syncthreads();  // Tbuf writes visible + Bb1 free (phase-1 kt=7 done)

        for (int kt = 0; kt < 8; ++kt) {
            if (kt < 7) {
                uint32_t* stg = (kt & 1) ? Bb0 : Bb1;
#pragma unroll
                for (int j = 0; j < 8; ++j)
                    stg[ob + j * 2] = to_tf32(pre[j]);
                if (kt < 6) {
#pragma unroll
                    for (int j = 0; j < 8; ++j)
                        pre[j] = W2p[(size_t)((kt + 2) * 16 + j * 2 + kk) * 128];
                }
            }
            mma_slab16(Tbuf, (kt & 1) ? Bb1 : Bb0, co, wm, wn, g, tig, kt);
            if (kt < 7) __syncthreads();
        }
    }

    gemm_epilogue<false, true, STATS>(co, b2, resid, C, 128, m0, 0,
                                      wm, wn, g, tig, tid, stats, (float*)Bb0);
}

// =====================================================================
// Flash-style BF16 attention v4: exp2-domain scores, occupancy 3.
// =====================================================================
constexpr int KP_ST = 12;
constexpr int VP_ST = 24;
constexpr int ATTN_SMEM = (512 * KP_ST + 256 * VP_ST) * 4;   // 48KB

__global__ void __launch_bounds__(256, 3)
attn_mma(const float* __restrict__ qkv, float* __restrict__ ao)
{
    extern __shared__ uint32_t sm[];
    uint32_t* Ksp = sm;                   // [512 kv][12]  bf16x2 pairs along d
    uint32_t* Vsp = sm + 512 * KP_ST;     // [256 kvpair][24] bf16x2 pairs along kv

    const int tid  = threadIdx.x;
    const int lane = tid & 31;
    const int warp = tid >> 5;
    const int g    = lane >> 2;
    const int tig  = lane & 3;
    const int b    = blockIdx.x;
    const int gi = b >> 4, h = (b >> 1) & 7, half = b & 1;
    const float* base = qkv + (size_t)gi * SEQ * 384;
    const int m0 = half * 256 + warp * 32;
    const float QSC = 0.25f * 1.44269504f;   // 1/sqrt(dh) * log2(e)

    for (int idx = tid; idx < 2048; idx += 256) {
        int r = idx >> 2, c4 = (idx & 3) * 4;
        float4 kv = *(const float4*)(base + (size_t)r * 384 + 128 + h * 16 + c4);
        Ksp[r * KP_ST + (c4 >> 1)]     = packbf(kv.x, kv.y);
        Ksp[r * KP_ST + (c4 >> 1) + 1] = packbf(kv.z, kv.w);
        if (idx < 1024) {
            int pr = r, dg = c4;
            float4 v0 = *(const float4*)(base + (size_t)(2 * pr)     * 384 + 256 + h * 16 + dg);
            float4 v1 = *(const float4*)(base + (size_t)(2 * pr + 1) * 384 + 256 + h * 16 + dg);
            uint32_t* vd = Vsp + pr * VP_ST + dg;
            vd[0] = packbf(v0.x, v1.x);
            vd[1] = packbf(v0.y, v1.y);
            vd[2] = packbf(v0.z, v1.z);
            vd[3] = packbf(v0.w, v1.w);
        }
    }

    uint32_t qa[2][4];
#pragma unroll
    for (int mt = 0; mt < 2; ++mt) {
        const float* qp = base + (size_t)(m0 + mt * 16 + g) * 384 + h * 16;
        float2 a0 = *(const float2*)(qp + 2 * tig);
        float2 a1 = *(const float2*)(qp + 8 * 384 + 2 * tig);
        float2 a2 = *(const float2*)(qp + 2 * tig + 8);
        float2 a3 = *(const float2*)(qp + 8 * 384 + 2 * tig + 8);
        qa[mt][0] = packbf(a0.x * QSC, a0.y * QSC);
        qa[mt][1] = packbf(a1.x * QSC, a1.y * QSC);
        qa[mt][2] = packbf(a2.x * QSC, a2.y * QSC);
        qa[mt][3] = packbf(a3.x * QSC, a3.y * QSC);
    }
    __syncthreads();

    float o[2][2][4];
    float lrow[2][2];
#pragma unroll
    for (int mt = 0; mt < 2; ++mt) {
        lrow[mt][0] = 0.f; lrow[mt][1] = 0.f;
#pragma unroll
        for (int nt = 0; nt < 2; ++nt)
#pragma unroll
            for (int r = 0; r < 4; ++r) o[mt][nt][r] = 0.f;
    }

    for (int j = 0; j < 16; ++j) {
        const int n0 = j * 32;
        uint32_t ps[2][2][4];

#pragma unroll
        for (int nt = 0; nt < 4; ++nt) {
            uint32_t bk[2];
            {
                const uint32_t* kp = Ksp + (n0 + nt * 8 + g) * KP_ST + tig;
                bk[0] = kp[0];
                bk[1] = kp[4];
            }
#pragma unroll
            for (int mt = 0; mt < 2; ++mt) {
                float c[4] = {0.f, 0.f, 0.f, 0.f};
                mma_bf16(c, qa[mt], bk);
                float p0 = fex2(c[0]);
                float p1 = fex2(c[1]);
                float p2 = fex2(c[2]);
                float p3 = fex2(c[3]);
                lrow[mt][0] += p0 + p1;
                lrow[mt][1] += p2 + p3;
                ps[mt][nt >> 1][(nt & 1) * 2 + 0] = packbf(p0, p1);
                ps[mt][nt >> 1][(nt & 1) * 2 + 1] = packbf(p2, p3);
            }
        }

#pragma unroll
        for (int c = 0; c < 2; ++c) {
            const int prb = (n0 >> 1) + c * 8;
#pragma unroll
            for (int nt = 0; nt < 2; ++nt) {
                uint32_t bv[2];
                const uint32_t* vp = Vsp + (prb + tig) * VP_ST + nt * 8 + g;
                bv[0] = vp[0];
                bv[1] = vp[4 * VP_ST];
#pragma unroll
                for (int mt = 0; mt < 2; ++mt)
                    mma_bf16(o[mt][nt], ps[mt][c], bv);
            }
        }
    }

#pragma unroll
    for (int mt = 0; mt < 2; ++mt) {
        float l0 = lrow[mt][0], l1 = lrow[mt][1];
        l0 += __shfl_xor_sync(0xffffffffu, l0, 1);
        l0 += __shfl_xor_sync(0xffffffffu, l0, 2);
        l1 += __shfl_xor_sync(0xffffffffu, l1, 1);
        l1 += __shfl_xor_sync(0xffffffffu, l1, 2);
        float i0 = 1.f / l0, i1 = 1.f / l1;
        int grow = gi * SEQ + m0 + mt * 16 + g;
#pragma unroll
        for (int nt = 0; nt < 2; ++nt) {
            int col = h * 16 + nt * 8 + 2 * tig;
            *(float2*)(ao + (size_t)grow * DD + col) =
                make_float2(o[mt][nt][0] * i0, o[mt][nt][1] * i0);
            *(float2*)(ao + (size_t)(grow + 8) * DD + col) =
                make_float2(o[mt][nt][2] * i1, o[mt][nt][3] * i1);
        }
    }
}

// =====================================================================
// BatchNorm applies
// =====================================================================
__device__ __forceinline__ void bn_coef(const float* stats, const float* gamma,
                                        const float* beta, int col,
                                        float& sc, float& sh)
{
    float mean = stats[col] * (1.f / (float)NN);
    float var  = stats[128 + col] * (1.f / (float)NN) - mean * mean;
    sc = gamma[col] * rsqrtf(var + 1e-5f);
    sh = beta[col] - mean * sc;
}

__global__ void __launch_bounds__(256)
bn_apply_one(const float* __restrict__ X, const float* __restrict__ stats,
             const float* __restrict__ gamma, const float* __restrict__ beta,
             float* __restrict__ out)
{
    int col = threadIdx.x & 127;
    int half = threadIdx.x >> 7;
    float sc, sh;
    bn_coef(stats, gamma, beta, col, sc, sh);
    int row0 = blockIdx.x * 128 + half * 64;
    size_t off = (size_t)row0 * DD + col;
#pragma unroll 4
    for (int r = 0; r < 64; ++r)
        out[off + r * DD] = X[off + r * DD] * sc + sh;
}

__global__ void __launch_bounds__(256)
bn_apply_dual(const float* __restrict__ ha, const float* __restrict__ statsA,
              const float* __restrict__ ga, const float* __restrict__ ba,
              const float* __restrict__ hl, const float* __restrict__ statsL,
              const float* __restrict__ gl, const float* __restrict__ bl,
              float* __restrict__ out)
{
    int col = threadIdx.x & 127;
    int half = threadIdx.x >> 7;
    float scA, shA, scL, shL;
    bn_coef(statsA, ga, ba, col, scA, shA);
    bn_coef(statsL, gl, bl, col, scL, shL);
    int row0 = blockIdx.x * 128 + half * 64;
    size_t off = (size_t)row0 * DD + col;
#pragma unroll 4
    for (int r = 0; r < 64; ++r)
        out[off + r * DD] = ha[off + r * DD] * scA + shA
                          + hl[off + r * DD] * scL + shL;
}

// =====================================================================
// Host launcher
// =====================================================================
extern "C" void kernel_launch(void* const* d_in, const int* in_sizes, int n_in,
                              void* d_out, int out_size)
{
    const float* x          = (const float*)d_in[0];
    const int*   edge_index = (const int*)  d_in[1];
    const float* edge_attr  = (const float*)d_in[2];
    const float* gin_w1     = (const float*)d_in[3];
    const float* gin_b1     = (const float*)d_in[4];
    const float* gin_w2     = (const float*)d_in[5];
    const float* gin_b2     = (const float*)d_in[6];
    const float* bn1l_g     = (const float*)d_in[7];
    const float* bn1l_b     = (const float*)d_in[8];
    const float* in_proj_w  = (const float*)d_in[9];
    const float* in_proj_b  = (const float*)d_in[10];
    const float* out_proj_w = (const float*)d_in[11];
    const float* out_proj_b = (const float*)d_in[12];
    const float* bn1a_g     = (const float*)d_in[13];
    const float* bn1a_b     = (const float*)d_in[14];
    const float* ff_w1      = (const float*)d_in[15];
    const float* ff_b1      = (const float*)d_in[16];
    const float* ff_w2      = (const float*)d_in[17];
    const float* ff_b2      = (const float*)d_in[18];
    const float* bn2_g      = (const float*)d_in[19];
    const float* bn2_b      = (const float*)d_in[20];
    float* out = (float*)d_out;

    cudaFuncSetAttribute(attn_mma, cudaFuncAttributeMaxDynamicSharedMemorySize, ATTN_SMEM);
    cudaFuncSetAttribute(gemm_ar<false, false>, cudaFuncAttributeMaxDynamicSharedMemorySize, GEMM_AR_SMEM);
    cudaFuncSetAttribute(gemm_ar<true,  true >, cudaFuncAttributeMaxDynamicSharedMemorySize, GEMM_AR_SMEM);
    cudaFuncSetAttribute(mlp_fused<1, true>, cudaFuncAttributeMaxDynamicSharedMemorySize, MLP_SMEM);
    cudaFuncSetAttribute(mlp_fused<2, true>, cudaFuncAttributeMaxDynamicSharedMemorySize, MLP_SMEM);

    float *z, *hl, *qkvb, *ao, *ha, *h, *h2, *stats;
    int *deg, *off, *pos, *eid;
    cudaGetSymbolAddress((void**)&z,    g_z);
    cudaGetSymbolAddress((void**)&hl,   g_hl);
    cudaGetSymbolAddress((void**)&qkvb, g_qkv);
    cudaGetSymbolAddress((void**)&ao,   g_ao);
    cudaGetSymbolAddress((void**)&ha,   g_ha);
    cudaGetSymbolAddress((void**)&h,    g_h);
    cudaGetSymbolAddress((void**)&h2,   g_h2);
    cudaGetSymbolAddress((void**)&stats, g_stats);
    cudaGetSymbolAddress((void**)&deg,  g_deg);
    cudaGetSymbolAddress((void**)&off,  g_off);
    cudaGetSymbolAddress((void**)&pos,  g_pos);
    cudaGetSymbolAddress((void**)&eid,  g_eid);

    const int* src = edge_index;
    const int* dst = edge_index + EE;
    const dim3 blk(256);
    const int GB = NN / 128;

    float* stats_hl = stats;
    float* stats_ha = stats + 256;
    float* stats_h2 = stats + 512;

    // launch order puts the QKV gemm_ar at profile index 3
    zero_misc<<<64, blk>>>(deg, stats);                                            // 0
    count_kernel<<<EE / 256, blk>>>(dst, deg);                                     // 1
    scan_kernel<<<1, 1024>>>(deg, off, pos);                                       // 2
    gemm_ar<false, false><<<dim3(GB, 3), blk, GEMM_AR_SMEM>>>(x, in_proj_w, in_proj_b,
                                                              nullptr, qkvb, 384, nullptr);  // 3 <- profiled
    attn_mma<<<NGR * NH * 2, blk, ATTN_SMEM>>>(qkvb, ao);                          // 4
    scatter_kernel<<<EE / 256, blk>>>(dst, pos, eid);                              // 5
    aggr_kernel<<<NN / 8, blk>>>(x, src, edge_attr, off, eid, z);                  // 6
    mlp_fused<1, true><<<GB, blk, MLP_SMEM>>>(z, gin_w1, gin_b1, gin_w2, gin_b2,
                                              x, hl, stats_hl);                    // 7
    gemm_ar<true, true><<<dim3(GB, 1), blk, GEMM_AR_SMEM>>>(ao, out_proj_w, out_proj_b,
                                                            x, ha, 128, stats_ha); // 8
    bn_apply_dual<<<128, blk>>>(ha, stats_ha, bn1a_g, bn1a_b,
                                hl, stats_hl, bn1l_g, bn1l_b, h);                  // 9
    mlp_fused<2, true><<<GB, blk, MLP_SMEM>>>(h, ff_w1, ff_b1, ff_w2, ff_b2,
                                              h, h2, stats_h2);                    // 10
    bn_apply_one<<<128, blk>>>(h2, stats_h2, bn2_g, bn2_b, out);                   // 11
}

// round 11
// speedup vs baseline: 1.4356x; 1.1592x over previous
#include <cuda_runtime.h>
#include <cuda_bf16.h>
#include <math.h>
#include <stdint.h>

// Problem constants
constexpr int NN  = 16384;   // nodes
constexpr int DD  = 128;     // dim
constexpr int EE  = 262144;  // edges
constexpr int SEQ = 512;     // nodes per graph
constexpr int NGR = 32;      // graphs
constexpr int NH  = 8;       // heads (dh = 16)

// ---------------- scratch ----------------
__device__ float g_z   [NN * DD];
__device__ float g_hl  [NN * DD];
__device__ float g_qkv [NN * 3 * DD];
__device__ float g_ao  [NN * DD];
__device__ float g_ha  [NN * DD];
__device__ float g_h   [NN * DD];
__device__ float g_h2  [NN * DD];
__device__ float g_stats[768];   // [0:256) hl, [256:512) ha, [512:768) h2
__device__ int   g_deg [NN];
__device__ int   g_off [NN + 1];
__device__ int   g_pos [NN];
__device__ int   g_eid [EE];

// =====================================================================
__global__ void zero_misc(int* deg, float* stats)
{
    int i = blockIdx.x * 256 + threadIdx.x;
    deg[i] = 0;
    if (i < 768) stats[i] = 0.f;
}

// =====================================================================
// CSR build by dst:  count -> scan -> scatter
// =====================================================================
__global__ void count_kernel(const int* __restrict__ dst, int* __restrict__ deg)
{
    int e = blockIdx.x * 256 + threadIdx.x;
    atomicAdd(&deg[dst[e]], 1);
}

__global__ void __launch_bounds__(1024)
scan_kernel(const int* __restrict__ deg, int* __restrict__ off, int* __restrict__ pos)
{
    __shared__ int buf[2][1024];
    int t = threadIdx.x;
    int base = t * 16;
    int loc[16];
    int sum = 0;
#pragma unroll
    for (int i = 0; i < 16; ++i) { loc[i] = sum; sum += deg[base + i]; }
    buf[0][t] = sum;
    __syncthreads();
    int sel = 0;
    for (int d = 1; d < 1024; d <<= 1) {
        int v = buf[sel][t] + (t >= d ? buf[sel][t - d] : 0);
        buf[sel ^ 1][t] = v;
        sel ^= 1;
        __syncthreads();
    }
    int excl = buf[sel][t] - sum;
#pragma unroll
    for (int i = 0; i < 16; ++i) {
        int o = excl + loc[i];
        off[base + i] = o;
        pos[base + i] = o;
    }
    if (t == 1023) off[NN] = excl + sum;
}

__global__ void scatter_kernel(const int* __restrict__ dst, int* __restrict__ pos,
                               int* __restrict__ eid)
{
    int e = blockIdx.x * 256 + threadIdx.x;
    int p = atomicAdd(&pos[dst[e]], 1);
    eid[p] = e;
}

// =====================================================================
// Gather aggregation: z = x + sum_{e -> node} relu(x[src[e]] + ea[e])
// =====================================================================
__global__ void __launch_bounds__(256)
aggr_kernel(const float* __restrict__ x, const int* __restrict__ src,
            const float* __restrict__ ea, const int* __restrict__ off,
            const int* __restrict__ eid, float* __restrict__ z)
{
    int node = blockIdx.x * 8 + (threadIdx.x >> 5);
    int lane = threadIdx.x & 31;
    int beg = off[node], end = off[node + 1];
    const float4* x4  = (const float4*)x;
    const float4* ea4 = (const float4*)ea;
    float4 acc = make_float4(0.f, 0.f, 0.f, 0.f);
#pragma unroll 2
    for (int i = beg; i < end; ++i) {
        int e = __ldg(eid + i);
        int s = __ldg(src + e);
        float4 a = x4[(size_t)s * 32 + lane];
        float4 b = ea4[(size_t)e * 32 + lane];
        acc.x += fmaxf(a.x + b.x, 0.f);
        acc.y += fmaxf(a.y + b.y, 0.f);
        acc.z += fmaxf(a.z + b.z, 0.f);
        acc.w += fmaxf(a.w + b.w, 0.f);
    }
    float4 xv = x4[(size_t)node * 32 + lane];
    ((float4*)z)[(size_t)node * 32 + lane] =
        make_float4(xv.x + acc.x, xv.y + acc.y, xv.z + acc.z, xv.w + acc.w);
}

// =====================================================================
// mma helpers
// =====================================================================
__device__ __forceinline__ uint32_t to_tf32(float f)
{
    uint32_t u;
    asm("cvt.rna.tf32.f32 %0, %1;" : "=r"(u) : "f"(f));
    return u;
}

__device__ __forceinline__ void mma_tf32(float c[4], const uint32_t a[4], const uint32_t b[2])
{
    asm volatile(
        "mma.sync.aligned.m16n8k8.row.col.f32.tf32.tf32.f32 "
        "{%0,%1,%2,%3}, {%4,%5,%6,%7}, {%8,%9}, {%0,%1,%2,%3};\n"
        : "+f"(c[0]), "+f"(c[1]), "+f"(c[2]), "+f"(c[3])
        : "r"(a[0]), "r"(a[1]), "r"(a[2]), "r"(a[3]), "r"(b[0]), "r"(b[1]));
}

// bf16 m16n8k16 mma, f32 accumulate
__device__ __forceinline__ void mma_bf16(float c[4], const uint32_t a[4], const uint32_t b[2])
{
    asm volatile(
        "mma.sync.aligned.m16n8k16.row.col.f32.bf16.bf16.f32 "
        "{%0,%1,%2,%3}, {%4,%5,%6,%7}, {%8,%9}, {%0,%1,%2,%3};\n"
        : "+f"(c[0]), "+f"(c[1]), "+f"(c[2]), "+f"(c[3])
        : "r"(a[0]), "r"(a[1]), "r"(a[2]), "r"(a[3]), "r"(b[0]), "r"(b[1]));
}

// pack two floats -> bf16x2 (lo = first k element)
__device__ __forceinline__ uint32_t packbf(float lo, float hi)
{
    uint32_t r;
    asm("cvt.rn.bf16x2.f32 %0, %1, %2;" : "=r"(r) : "f"(hi), "f"(lo));
    return r;
}

__device__ __forceinline__ float fex2(float x)
{
    float y;
    asm("ex2.approx.f32 %0, %1;" : "=f"(y) : "f"(x));
    return y;
}

constexpr int AST = 132;   // A/T smem stride (u32)
constexpr int BST = 20;    // B-chunk smem stride

// one 16-k-slab of mma: A-src (stride AST), B-chunk (stride BST)
__device__ __forceinline__ void mma_slab16(const uint32_t* S, const uint32_t* Bb,
                                           float acc[4][4][4],
                                           int wm, int wn, int g, int tig, int kt)
{
#pragma unroll
    for (int k8s = 0; k8s < 2; ++k8s) {
        const int kk = kt * 16 + k8s * 8;
        uint32_t af[4][4];
#pragma unroll
        for (int mf = 0; mf < 4; ++mf) {
            const uint32_t* pa = S + (wm * 64 + mf * 16 + g) * AST + kk + tig;
            af[mf][0] = pa[0];
            af[mf][1] = pa[8 * AST];
            af[mf][2] = pa[4];
            af[mf][3] = pa[8 * AST + 4];
        }
        uint32_t bf[4][2];
#pragma unroll
        for (int nf = 0; nf < 4; ++nf) {
            const uint32_t* pb = Bb + (wn * 32 + nf * 8 + g) * BST + k8s * 8 + tig;
            bf[nf][0] = pb[0];
            bf[nf][1] = pb[4];
        }
#pragma unroll
        for (int mf = 0; mf < 4; ++mf)
#pragma unroll
            for (int nf = 0; nf < 4; ++nf)
                mma_tf32(acc[mf][nf], af[mf], bf[nf]);
    }
}

// epilogue shared by gemm_ar / mlp_fused
template<bool RELU, bool RESID, bool STATS>
__device__ __forceinline__ void gemm_epilogue(
    float acc[4][4][4], const float* bias, const float* resid,
    float* C, int ldc, int m0, int n0,
    int wm, int wn, int g, int tig, int tid,
    float* stats, float* sst /* 256-float smem scratch */)
{
    float cs[8], cq[8];
    if (STATS) {
#pragma unroll
        for (int j = 0; j < 8; ++j) { cs[j] = 0.f; cq[j] = 0.f; }
    }
#pragma unroll
    for (int mf = 0; mf < 4; ++mf) {
#pragma unroll
        for (int nf = 0; nf < 4; ++nf) {
            int row = m0 + wm * 64 + mf * 16 + g;
            int col = n0 + wn * 32 + nf * 8 + 2 * tig;
            float b0 = bias[col], b1 = bias[col + 1];
            float o00 = acc[mf][nf][0] + b0, o01 = acc[mf][nf][1] + b1;
            float o10 = acc[mf][nf][2] + b0, o11 = acc[mf][nf][3] + b1;
            if (RELU) {
                o00 = fmaxf(o00, 0.f); o01 = fmaxf(o01, 0.f);
                o10 = fmaxf(o10, 0.f); o11 = fmaxf(o11, 0.f);
            }
            if (RESID) {
                float2 r0 = *(const float2*)(resid + (size_t)row * ldc + col);
                float2 r1 = *(const float2*)(resid + (size_t)(row + 8) * ldc + col);
                o00 += r0.x; o01 += r0.y;
                o10 += r1.x; o11 += r1.y;
            }
            if (STATS) {
                cs[nf*2]   += o00 + o10;
                cs[nf*2+1] += o01 + o11;
                cq[nf*2]   += o00*o00 + o10*o10;
                cq[nf*2+1] += o01*o01 + o11*o11;
            }
            *(float2*)(C + (size_t)row * ldc + col)       = make_float2(o00, o01);
            *(float2*)(C + (size_t)(row + 8) * ldc + col) = make_float2(o10, o11);
        }
    }
    if (STATS) {
        __syncthreads();
        sst[tid] = 0.f;
        __syncthreads();
#pragma unroll
        for (int j = 0; j < 8; ++j) {
            int col = wn * 32 + (j >> 1) * 8 + 2 * tig + (j & 1);
            atomicAdd(&sst[col],       cs[j]);
            atomicAdd(&sst[128 + col], cq[j]);
        }
        __syncthreads();
        atomicAdd(&stats[tid], sst[tid]);
    }
}

// =====================================================================
// A-resident GEMM (K=128): C = A[128rows,128] @ B^T + bias (+resid)(+stats)
// Double-buffered B chunks: ONE sync per k-chunk.
// =====================================================================
constexpr int GEMM_AR_SMEM = (128 * AST + 2 * 128 * BST) * 4;

template<bool RESID, bool STATS>
__global__ void __launch_bounds__(256, 2)
gemm_ar(const float* __restrict__ A,
        const float* __restrict__ B,
        const float* __restrict__ bias,
        const float* __restrict__ resid,
        float* __restrict__ C, int ldc,
        float* __restrict__ stats)
{
    extern __shared__ uint32_t sm[];
    uint32_t* Abuf = sm;               // [128][AST]
    uint32_t* Bb0  = sm + 128 * AST;   // stage 0
    uint32_t* Bb1  = Bb0 + 128 * BST;  // stage 1

    const int tid = threadIdx.x;
    const int lane = tid & 31, warp = tid >> 5;
    const int wm = warp >> 2, wn = warp & 3;
    const int g = lane >> 2, tig = lane & 3;
    const int m0 = blockIdx.x * 128;
    const int n0 = blockIdx.y * 128;
    const int i0 = tid, i1 = tid + 256;
    const float* Bp0 = B + (size_t)(n0 + (i0 >> 2)) * 128 + (i0 & 3) * 4;
    const float* Bp1 = B + (size_t)(n0 + (i1 >> 2)) * 128 + (i1 & 3) * 4;
    const int o0 = (i0 >> 2) * BST + (i0 & 3) * 4;   // ELEMENT offsets
    const int o1 = (i1 >> 2) * BST + (i1 & 3) * 4;

#pragma unroll
    for (int it = 0; it < 16; ++it) {
        int idx = tid + it * 256;
        int r = idx >> 5, c4 = (idx & 31) * 4;
        float4 v = *(const float4*)(A + (size_t)(m0 + r) * 128 + c4);
        uint32_t* d = Abuf + r * AST + c4;
        d[0] = to_tf32(v.x); d[1] = to_tf32(v.y);
        d[2] = to_tf32(v.z); d[3] = to_tf32(v.w);
    }

    float acc[4][4][4];
#pragma unroll
    for (int i = 0; i < 4; ++i)
#pragma unroll
        for (int j = 0; j < 4; ++j)
#pragma unroll
            for (int r = 0; r < 4; ++r) acc[i][j][r] = 0.f;

    // chunk 0 -> stage 0, prefetch chunk 1
    float4 pre0 = *(const float4*)(Bp0);
    float4 pre1 = *(const float4*)(Bp1);
    {
        uint32_t* d0 = Bb0 + o0;
        d0[0] = to_tf32(pre0.x); d0[1] = to_tf32(pre0.y);
        d0[2] = to_tf32(pre0.z); d0[3] = to_tf32(pre0.w);
        uint32_t* d1 = Bb0 + o1;
        d1[0] = to_tf32(pre1.x); d1[1] = to_tf32(pre1.y);
        d1[2] = to_tf32(pre1.z); d1[3] = to_tf32(pre1.w);
    }
    pre0 = *(const float4*)(Bp0 + 16);
    pre1 = *(const float4*)(Bp1 + 16);
    __syncthreads();

    for (int kt = 0; kt < 8; ++kt) {
        if (kt < 7) {
            uint32_t* stg = (kt & 1) ? Bb0 : Bb1;   // stage (kt+1)&1
            uint32_t* d0 = stg + o0;
            d0[0] = to_tf32(pre0.x); d0[1] = to_tf32(pre0.y);
            d0[2] = to_tf32(pre0.z); d0[3] = to_tf32(pre0.w);
            uint32_t* d1 = stg + o1;
            d1[0] = to_tf32(pre1.x); d1[1] = to_tf32(pre1.y);
            d1[2] = to_tf32(pre1.z); d1[3] = to_tf32(pre1.w);
            if (kt < 6) {
                pre0 = *(const float4*)(Bp0 + (kt + 2) * 16);
                pre1 = *(const float4*)(Bp1 + (kt + 2) * 16);
            }
        }
        mma_slab16(Abuf, (kt & 1) ? Bb1 : Bb0, acc, wm, wn, g, tig, kt);
        if (kt < 7) __syncthreads();
    }

    gemm_epilogue<false, RESID, STATS>(acc, bias, resid, C, ldc, m0, n0,
                                       wm, wn, g, tig, tid, stats, (float*)Bb0);
}

// =====================================================================
// Fused MLP: C = relu(A @ W1 + b1) @ W2 + b2 (+resid)(+stats)
// Double-buffered B chunks, one sync per chunk.
// =====================================================================
constexpr int MLP_SMEM = (2 * 128 * AST + 2 * 128 * BST) * 4;

template<int NC, bool STATS>
__global__ void __launch_bounds__(256, 1)
mlp_fused(const float* __restrict__ A,
          const float* __restrict__ W1, const float* __restrict__ b1,
          const float* __restrict__ W2, const float* __restrict__ b2,
          const float* __restrict__ resid,
          float* __restrict__ C,
          float* __restrict__ stats)
{
    extern __shared__ uint32_t sm[];
    uint32_t* Abuf = sm;                   // [128][AST]
    uint32_t* Tbuf = sm + 128 * AST;       // [128][AST]
    uint32_t* Bb0  = sm + 2 * 128 * AST;   // stage 0
    uint32_t* Bb1  = Bb0 + 128 * BST;      // stage 1

    const int tid = threadIdx.x;
    const int lane = tid & 31, warp = tid >> 5;
    const int wm = warp >> 2, wn = warp & 3;
    const int g = lane >> 2, tig = lane & 3;
    const int m0 = blockIdx.x * 128;
    const int ldw1 = NC * 128;

    const int kk = tid >> 7;        // 0..1
    const int nn2 = tid & 127;      // n col
    const int ob = nn2 * BST + kk;  // ELEMENT store offset base

#pragma unroll
    for (int it = 0; it < 16; ++it) {
        int idx = tid + it * 256;
        int r = idx >> 5, c4 = (idx & 31) * 4;
        float4 v = *(const float4*)(A + (size_t)(m0 + r) * 128 + c4);
        uint32_t* d = Abuf + r * AST + c4;
        d[0] = to_tf32(v.x); d[1] = to_tf32(v.y);
        d[2] = to_tf32(v.z); d[3] = to_tf32(v.w);
    }

    float co[4][4][4];
#pragma unroll
    for (int i = 0; i < 4; ++i)
#pragma unroll
        for (int j = 0; j < 4; ++j)
#pragma unroll
            for (int r = 0; r < 4; ++r) co[i][j][r] = 0.f;

#pragma unroll
    for (int nc = 0; nc < NC; ++nc) {
        // ============ phase 1: c1 = A @ W1[:, nc*128..] ============
        float c1[4][4][4];
#pragma unroll
        for (int i = 0; i < 4; ++i)
#pragma unroll
            for (int j = 0; j < 4; ++j)
#pragma unroll
                for (int r = 0; r < 4; ++r) c1[i][j][r] = 0.f;

        const float* Wp = W1 + nc * 128 + nn2;
        float pre[8];
#pragma unroll
        for (int j = 0; j < 8; ++j)
            pre[j] = Wp[(size_t)(j * 2 + kk) * ldw1];
        if (nc) __syncthreads();  // protect Bb0 from previous phase-2 kt=6 reads
#pragma unroll
        for (int j = 0; j < 8; ++j)
            Bb0[ob + j * 2] = to_tf32(pre[j]);
#pragma unroll
        for (int j = 0; j < 8; ++j)
            pre[j] = Wp[(size_t)(16 + j * 2 + kk) * ldw1];
        __syncthreads();

        for (int kt = 0; kt < 8; ++kt) {
            if (kt < 7) {
                uint32_t* stg = (kt & 1) ? Bb0 : Bb1;
#pragma unroll
                for (int j = 0; j < 8; ++j)
                    stg[ob + j * 2] = to_tf32(pre[j]);
                if (kt < 6) {
#pragma unroll
                    for (int j = 0; j < 8; ++j)
                        pre[j] = Wp[(size_t)((kt + 2) * 16 + j * 2 + kk) * ldw1];
                }
            }
            mma_slab16(Abuf, (kt & 1) ? Bb1 : Bb0, c1, wm, wn, g, tig, kt);
            if (kt < 7) __syncthreads();
        }

        // write hidden tile: relu(c1 + b1chunk) -> Tbuf (tf32)
#pragma unroll
        for (int mf = 0; mf < 4; ++mf) {
#pragma unroll
            for (int nf = 0; nf < 4; ++nf) {
                int row = wm * 64 + mf * 16 + g;
                int col = wn * 32 + nf * 8 + 2 * tig;
                float bb0 = b1[nc * 128 + col], bb1 = b1[nc * 128 + col + 1];
                Tbuf[row * AST + col]           = to_tf32(fmaxf(c1[mf][nf][0] + bb0, 0.f));
                Tbuf[row * AST + col + 1]       = to_tf32(fmaxf(c1[mf][nf][1] + bb1, 0.f));
                Tbuf[(row + 8) * AST + col]     = to_tf32(fmaxf(c1[mf][nf][2] + bb0, 0.f));
                Tbuf[(row + 8) * AST + col + 1] = to_tf32(fmaxf(c1[mf][nf][3] + bb1, 0.f));
            }
        }

        // ============ phase 2: co += T @ W2[nc*128.., :] ============
        const float* W2p = W2 + (size_t)nc * 128 * 128 + nn2;
#pragma unroll
        for (int j = 0; j < 8; ++j)
            pre[j] = W2p[(size_t)(j * 2 + kk) * 128];
        __syncthreads();  // all warps past phase-1 kt=6 mma (Bb0 free)
#pragma unroll
        for (int j = 0; j < 8; ++j)
            Bb0[ob + j * 2] = to_tf32(pre[j]);
#pragma unroll
        for (int j = 0; j < 8; ++j)
            pre[j] = W2p[(size_t)(16 + j * 2 + kk) * 128];
        __syncthreads();  // Tbuf writes visible + Bb1 free (phase-1 kt=7 done)

        for (int kt = 0; kt < 8; ++kt) {
            if (kt < 7) {
                uint32_t* stg = (kt & 1) ? Bb0 : Bb1;
#pragma unroll
                for (int j = 0; j < 8; ++j)
                    stg[ob + j * 2] = to_tf32(pre[j]);
                if (kt < 6) {
#pragma unroll
                    for (int j = 0; j < 8; ++j)
                        pre[j] = W2p[(size_t)((kt + 2) * 16 + j * 2 + kk) * 128];
                }
            }
            mma_slab16(Tbuf, (kt & 1) ? Bb1 : Bb0, co, wm, wn, g, tig, kt);
            if (kt < 7) __syncthreads();
        }
    }

    gemm_epilogue<false, true, STATS>(co, b2, resid, C, 128, m0, 0,
                                      wm, wn, g, tig, tid, stats, (float*)Bb0);
}

// =====================================================================
// Flash-style BF16 attention v4: exp2-domain scores, occupancy 3.
// =====================================================================
constexpr int KP_ST = 12;
constexpr int VP_ST = 24;
constexpr int ATTN_SMEM = (512 * KP_ST + 256 * VP_ST) * 4;   // 48KB

__global__ void __launch_bounds__(256, 3)
attn_mma(const float* __restrict__ qkv, float* __restrict__ ao)
{
    extern __shared__ uint32_t sm[];
    uint32_t* Ksp = sm;                   // [512 kv][12]  bf16x2 pairs along d
    uint32_t* Vsp = sm + 512 * KP_ST;     // [256 kvpair][24] bf16x2 pairs along kv

    const int tid  = threadIdx.x;
    const int lane = tid & 31;
    const int warp = tid >> 5;
    const int g    = lane >> 2;
    const int tig  = lane & 3;
    const int b    = blockIdx.x;
    const int gi = b >> 4, h = (b >> 1) & 7, half = b & 1;
    const float* base = qkv + (size_t)gi * SEQ * 384;
    const int m0 = half * 256 + warp * 32;
    const float QSC = 0.25f * 1.44269504f;   // 1/sqrt(dh) * log2(e)

    for (int idx = tid; idx < 2048; idx += 256) {
        int r = idx >> 2, c4 = (idx & 3) * 4;
        float4 kv = *(const float4*)(base + (size_t)r * 384 + 128 + h * 16 + c4);
        Ksp[r * KP_ST + (c4 >> 1)]     = packbf(kv.x, kv.y);
        Ksp[r * KP_ST + (c4 >> 1) + 1] = packbf(kv.z, kv.w);
        if (idx < 1024) {
            int pr = r, dg = c4;
            float4 v0 = *(const float4*)(base + (size_t)(2 * pr)     * 384 + 256 + h * 16 + dg);
            float4 v1 = *(const float4*)(base + (size_t)(2 * pr + 1) * 384 + 256 + h * 16 + dg);
            uint32_t* vd = Vsp + pr * VP_ST + dg;
            vd[0] = packbf(v0.x, v1.x);
            vd[1] = packbf(v0.y, v1.y);
            vd[2] = packbf(v0.z, v1.z);
            vd[3] = packbf(v0.w, v1.w);
        }
    }

    uint32_t qa[2][4];
#pragma unroll
    for (int mt = 0; mt < 2; ++mt) {
        const float* qp = base + (size_t)(m0 + mt * 16 + g) * 384 + h * 16;
        float2 a0 = *(const float2*)(qp + 2 * tig);
        float2 a1 = *(const float2*)(qp + 8 * 384 + 2 * tig);
        float2 a2 = *(const float2*)(qp + 2 * tig + 8);
        float2 a3 = *(const float2*)(qp + 8 * 384 + 2 * tig + 8);
        qa[mt][0] = packbf(a0.x * QSC, a0.y * QSC);
        qa[mt][1] = packbf(a1.x * QSC, a1.y * QSC);
        qa[mt][2] = packbf(a2.x * QSC, a2.y * QSC);
        qa[mt][3] = packbf(a3.x * QSC, a3.y * QSC);
    }
    __syncthreads();

    float o[2][2][4];
    float lrow[2][2];
#pragma unroll
    for (int mt = 0; mt < 2; ++mt) {
        lrow[mt][0] = 0.f; lrow[mt][1] = 0.f;
#pragma unroll
        for (int nt = 0; nt < 2; ++nt)
#pragma unroll
            for (int r = 0; r < 4; ++r) o[mt][nt][r] = 0.f;
    }

    for (int j = 0; j < 16; ++j) {
        const int n0 = j * 32;
        uint32_t ps[2][2][4];

#pragma unroll
        for (int nt = 0; nt < 4; ++nt) {
            uint32_t bk[2];
            {
                const uint32_t* kp = Ksp + (n0 + nt * 8 + g) * KP_ST + tig;
                bk[0] = kp[0];
                bk[1] = kp[4];
            }
#pragma unroll
            for (int mt = 0; mt < 2; ++mt) {
                float c[4] = {0.f, 0.f, 0.f, 0.f};
                mma_bf16(c, qa[mt], bk);
                float p0 = fex2(c[0]);
                float p1 = fex2(c[1]);
                float p2 = fex2(c[2]);
                float p3 = fex2(c[3]);
                lrow[mt][0] += p0 + p1;
                lrow[mt][1] += p2 + p3;
                ps[mt][nt >> 1][(nt & 1) * 2 + 0] = packbf(p0, p1);
                ps[mt][nt >> 1][(nt & 1) * 2 + 1] = packbf(p2, p3);
            }
        }

#pragma unroll
        for (int c = 0; c < 2; ++c) {
            const int prb = (n0 >> 1) + c * 8;
#pragma unroll
            for (int nt = 0; nt < 2; ++nt) {
                uint32_t bv[2];
                const uint32_t* vp = Vsp + (prb + tig) * VP_ST + nt * 8 + g;
                bv[0] = vp[0];
                bv[1] = vp[4 * VP_ST];
#pragma unroll
                for (int mt = 0; mt < 2; ++mt)
                    mma_bf16(o[mt][nt], ps[mt][c], bv);
            }
        }
    }

#pragma unroll
    for (int mt = 0; mt < 2; ++mt) {
        float l0 = lrow[mt][0], l1 = lrow[mt][1];
        l0 += __shfl_xor_sync(0xffffffffu, l0, 1);
        l0 += __shfl_xor_sync(0xffffffffu, l0, 2);
        l1 += __shfl_xor_sync(0xffffffffu, l1, 1);
        l1 += __shfl_xor_sync(0xffffffffu, l1, 2);
        float i0 = 1.f / l0, i1 = 1.f / l1;
        int grow = gi * SEQ + m0 + mt * 16 + g;
#pragma unroll
        for (int nt = 0; nt < 2; ++nt) {
            int col = h * 16 + nt * 8 + 2 * tig;
            *(float2*)(ao + (size_t)grow * DD + col) =
                make_float2(o[mt][nt][0] * i0, o[mt][nt][1] * i0);
            *(float2*)(ao + (size_t)(grow + 8) * DD + col) =
                make_float2(o[mt][nt][2] * i1, o[mt][nt][3] * i1);
        }
    }
}

// =====================================================================
// BatchNorm applies
// =====================================================================
__device__ __forceinline__ void bn_coef(const float* stats, const float* gamma,
                                        const float* beta, int col,
                                        float& sc, float& sh)
{
    float mean = stats[col] * (1.f / (float)NN);
    float var  = stats[128 + col] * (1.f / (float)NN) - mean * mean;
    sc = gamma[col] * rsqrtf(var + 1e-5f);
    sh = beta[col] - mean * sc;
}

__global__ void __launch_bounds__(256)
bn_apply_one(const float* __restrict__ X, const float* __restrict__ stats,
             const float* __restrict__ gamma, const float* __restrict__ beta,
             float* __restrict__ out)
{
    int col = threadIdx.x & 127;
    int half = threadIdx.x >> 7;
    float sc, sh;
    bn_coef(stats, gamma, beta, col, sc, sh);
    int row0 = blockIdx.x * 128 + half * 64;
    size_t off = (size_t)row0 * DD + col;
#pragma unroll 4
    for (int r = 0; r < 64; ++r)
        out[off + r * DD] = X[off + r * DD] * sc + sh;
}

__global__ void __launch_bounds__(256)
bn_apply_dual(const float* __restrict__ ha, const float* __restrict__ statsA,
              const float* __restrict__ ga, const float* __restrict__ ba,
              const float* __restrict__ hl, const float* __restrict__ statsL,
              const float* __restrict__ gl, const float* __restrict__ bl,
              float* __restrict__ out)
{
    int col = threadIdx.x & 127;
    int half = threadIdx.x >> 7;
    float scA, shA, scL, shL;
    bn_coef(statsA, ga, ba, col, scA, shA);
    bn_coef(statsL, gl, bl, col, scL, shL);
    int row0 = blockIdx.x * 128 + half * 64;
    size_t off = (size_t)row0 * DD + col;
#pragma unroll 4
    for (int r = 0; r < 64; ++r)
        out[off + r * DD] = ha[off + r * DD] * scA + shA
                          + hl[off + r * DD] * scL + shL;
}

// =====================================================================
// Host launcher — two-stream fork/join captured as a branching graph.
// Stream creation happens on the first (uncaptured correctness) call;
// during capture only event record/wait + launches are issued.
// =====================================================================
extern "C" void kernel_launch(void* const* d_in, const int* in_sizes, int n_in,
                              void* d_out, int out_size)
{
    const float* x          = (const float*)d_in[0];
    const int*   edge_index = (const int*)  d_in[1];
    const float* edge_attr  = (const float*)d_in[2];
    const float* gin_w1     = (const float*)d_in[3];
    const float* gin_b1     = (const float*)d_in[4];
    const float* gin_w2     = (const float*)d_in[5];
    const float* gin_b2     = (const float*)d_in[6];
    const float* bn1l_g     = (const float*)d_in[7];
    const float* bn1l_b     = (const float*)d_in[8];
    const float* in_proj_w  = (const float*)d_in[9];
    const float* in_proj_b  = (const float*)d_in[10];
    const float* out_proj_w = (const float*)d_in[11];
    const float* out_proj_b = (const float*)d_in[12];
    const float* bn1a_g     = (const float*)d_in[13];
    const float* bn1a_b     = (const float*)d_in[14];
    const float* ff_w1      = (const float*)d_in[15];
    const float* ff_b1      = (const float*)d_in[16];
    const float* ff_w2      = (const float*)d_in[17];
    const float* ff_b2      = (const float*)d_in[18];
    const float* bn2_g      = (const float*)d_in[19];
    const float* bn2_b      = (const float*)d_in[20];
    float* out = (float*)d_out;

    // One-time resources (created outside capture on the correctness call).
    static cudaStream_t sB = nullptr;
    static cudaEvent_t evFork = nullptr, evJoin = nullptr;
    if (sB == nullptr) {
        cudaStreamCreateWithFlags(&sB, cudaStreamNonBlocking);
        cudaEventCreateWithFlags(&evFork, cudaEventDisableTiming);
        cudaEventCreateWithFlags(&evJoin, cudaEventDisableTiming);
        cudaFuncSetAttribute(attn_mma, cudaFuncAttributeMaxDynamicSharedMemorySize, ATTN_SMEM);
        cudaFuncSetAttribute(gemm_ar<false, false>, cudaFuncAttributeMaxDynamicSharedMemorySize, GEMM_AR_SMEM);
        cudaFuncSetAttribute(gemm_ar<true,  true >, cudaFuncAttributeMaxDynamicSharedMemorySize, GEMM_AR_SMEM);
        cudaFuncSetAttribute(mlp_fused<1, true>, cudaFuncAttributeMaxDynamicSharedMemorySize, MLP_SMEM);
        cudaFuncSetAttribute(mlp_fused<2, true>, cudaFuncAttributeMaxDynamicSharedMemorySize, MLP_SMEM);
    }

    float *z, *hl, *qkvb, *ao, *ha, *h, *h2, *stats;
    int *deg, *off, *pos, *eid;
    cudaGetSymbolAddress((void**)&z,    g_z);
    cudaGetSymbolAddress((void**)&hl,   g_hl);
    cudaGetSymbolAddress((void**)&qkvb, g_qkv);
    cudaGetSymbolAddress((void**)&ao,   g_ao);
    cudaGetSymbolAddress((void**)&ha,   g_ha);
    cudaGetSymbolAddress((void**)&h,    g_h);
    cudaGetSymbolAddress((void**)&h2,   g_h2);
    cudaGetSymbolAddress((void**)&stats, g_stats);
    cudaGetSymbolAddress((void**)&deg,  g_deg);
    cudaGetSymbolAddress((void**)&off,  g_off);
    cudaGetSymbolAddress((void**)&pos,  g_pos);
    cudaGetSymbolAddress((void**)&eid,  g_eid);

    const int* src = edge_index;
    const int* dst = edge_index + EE;
    const dim3 blk(256);
    const int GB = NN / 128;

    float* stats_hl = stats;
    float* stats_ha = stats + 256;
    float* stats_h2 = stats + 512;

    // ---- common prologue on null stream ----
    zero_misc<<<64, blk>>>(deg, stats);                                            // launch 0

    // ---- fork: stream B = attention branch ----
    cudaEventRecord(evFork, 0);
    cudaStreamWaitEvent(sB, evFork, 0);

    gemm_ar<false, false><<<dim3(GB, 3), blk, GEMM_AR_SMEM, sB>>>(
        x, in_proj_w, in_proj_b, nullptr, qkvb, 384, nullptr);                     // 1 (B)
    count_kernel<<<EE / 256, blk>>>(dst, deg);                                     // 2 (A)
    attn_mma<<<NGR * NH * 2, blk, ATTN_SMEM, sB>>>(qkvb, ao);                      // 3 (B) <- profiled
    scan_kernel<<<1, 1024>>>(deg, off, pos);                                       // 4 (A)
    scatter_kernel<<<EE / 256, blk>>>(dst, pos, eid);                              // 5 (A)
    gemm_ar<true, true><<<dim3(GB, 1), blk, GEMM_AR_SMEM, sB>>>(
        ao, out_proj_w, out_proj_b, x, ha, 128, stats_ha);                         // 6 (B)
    aggr_kernel<<<NN / 8, blk>>>(x, src, edge_attr, off, eid, z);                  // 7 (A)
    mlp_fused<1, true><<<GB, blk, MLP_SMEM>>>(z, gin_w1, gin_b1, gin_w2, gin_b2,
                                              x, hl, stats_hl);                    // 8 (A)

    // ---- join ----
    cudaEventRecord(evJoin, sB);
    cudaStreamWaitEvent(0, evJoin, 0);

    bn_apply_dual<<<128, blk>>>(ha, stats_ha, bn1a_g, bn1a_b,
                                hl, stats_hl, bn1l_g, bn1l_b, h);                  // 9
    mlp_fused<2, true><<<GB, blk, MLP_SMEM>>>(h, ff_w1, ff_b1, ff_w2, ff_b2,
                                              h, h2, stats_h2);                    // 10
    bn_apply_one<<<128, blk>>>(h2, stats_h2, bn2_g, bn2_b, out);                   // 11
}